// round 1
// baseline (speedup 1.0000x reference)
#include <cuda_runtime.h>
#include <cuda_bf16.h>
#include <math.h>

// Problem constants
#define BATCH 2
#define SEQ   2048
#define DMODEL 512
#define NHEAD 8
#define HDIM  64
#define WIN   32           // half-window
#define WFULL 65           // 2*WIN+1

// Scratch buffers (device globals -- no allocation allowed)
__device__ float g_qkv[BATCH * SEQ * 3 * DMODEL];   // [B,S,1536] = [q|k|v] x [h][d]
__device__ float g_attn[BATCH * SEQ * DMODEL];      // attention output [B,S,512]

// ---------------------------------------------------------------------------
// Tiled SGEMM with bias: C[M,N] = A[M,K] @ B[K,N] + bias[N]
// Block tile 128x128, BK=8, 256 threads, 8x8 per-thread register tile
// (split 4+4 rows/cols for conflict-free float4 smem access).
// Assumes M%128==0, N%128==0, K%8==0, all row pointers 16B-aligned.
// ---------------------------------------------------------------------------
__global__ __launch_bounds__(256) void sgemm_bias_kernel(
    const float* __restrict__ A, const float* __restrict__ B,
    const float* __restrict__ bias, float* __restrict__ C,
    int M, int N, int K)
{
    __shared__ float As[8][128];   // [k][m] (transposed stage)
    __shared__ float Bs[8][128];   // [k][n]

    const int tid = threadIdx.x;
    const int bn = blockIdx.x * 128;
    const int bm = blockIdx.y * 128;
    const int tx = tid & 15;       // 16 threads across N
    const int ty = tid >> 4;       // 16 threads across M

    // Global-load index mapping
    const int arow = tid >> 1;            // 0..127
    const int acol = (tid & 1) << 2;      // 0 or 4
    const int brow = tid >> 5;            // 0..7
    const int bcol = (tid & 31) << 2;     // 0..124

    const float* Aptr = A + (size_t)(bm + arow) * K + acol;
    const float* Bptr = B + (size_t)brow * N + bn + bcol;

    float acc[8][8];
    #pragma unroll
    for (int i = 0; i < 8; ++i)
        #pragma unroll
        for (int j = 0; j < 8; ++j) acc[i][j] = 0.0f;

    const int nk = K >> 3;

    // stage 0 prefetch into registers
    float4 av = *(const float4*)(Aptr);
    float4 bv = *(const float4*)(Bptr);

    for (int t = 0; t < nk; ++t) {
        // commit staged registers to smem
        As[acol + 0][arow] = av.x;
        As[acol + 1][arow] = av.y;
        As[acol + 2][arow] = av.z;
        As[acol + 3][arow] = av.w;
        *(float4*)&Bs[brow][bcol] = bv;
        __syncthreads();

        // prefetch next tile while computing this one
        if (t + 1 < nk) {
            av = *(const float4*)(Aptr + (t + 1) * 8);
            bv = *(const float4*)(Bptr + (size_t)(t + 1) * 8 * N);
        }

        #pragma unroll
        for (int kk = 0; kk < 8; ++kk) {
            float4 a0 = *(const float4*)&As[kk][ty * 4];
            float4 a1 = *(const float4*)&As[kk][64 + ty * 4];
            float4 b0 = *(const float4*)&Bs[kk][tx * 4];
            float4 b1 = *(const float4*)&Bs[kk][64 + tx * 4];
            float a[8] = {a0.x, a0.y, a0.z, a0.w, a1.x, a1.y, a1.z, a1.w};
            float b[8] = {b0.x, b0.y, b0.z, b0.w, b1.x, b1.y, b1.z, b1.w};
            #pragma unroll
            for (int i = 0; i < 8; ++i)
                #pragma unroll
                for (int j = 0; j < 8; ++j)
                    acc[i][j] = fmaf(a[i], b[j], acc[i][j]);
        }
        __syncthreads();
    }

    // epilogue: bias + store (two float4 per row)
    float4 bias0 = *(const float4*)(bias + bn + tx * 4);
    float4 bias1 = *(const float4*)(bias + bn + 64 + tx * 4);

    #pragma unroll
    for (int i = 0; i < 8; ++i) {
        int rowoff = (i < 4) ? (ty * 4 + i) : (64 + ty * 4 + (i - 4));
        float* Cp = C + (size_t)(bm + rowoff) * N + bn;
        float4 v0, v1;
        v0.x = acc[i][0] + bias0.x;
        v0.y = acc[i][1] + bias0.y;
        v0.z = acc[i][2] + bias0.z;
        v0.w = acc[i][3] + bias0.w;
        v1.x = acc[i][4] + bias1.x;
        v1.y = acc[i][5] + bias1.y;
        v1.z = acc[i][6] + bias1.z;
        v1.w = acc[i][7] + bias1.w;
        *(float4*)(Cp + tx * 4) = v0;
        *(float4*)(Cp + 64 + tx * 4) = v1;
    }
}

// ---------------------------------------------------------------------------
// Sliding-window attention.
// One CTA handles (b, h, 64 consecutive queries). 512 threads = 16 warps,
// each warp owns 4 queries (processed serially).
// Shared: K window [128 rows x 65 floats pad], V window [128 x 65], Q [64 x 64].
// Window row r corresponds to position s0 - 32 + r; out-of-range rows zeroed.
// Query qi's window entry j lives at window row (qi + j).
// ---------------------------------------------------------------------------
#define ATT_SMEM_FLOATS (2 * 128 * 65 + 64 * 64)

__global__ __launch_bounds__(512) void attn_window_kernel(
    const float* __restrict__ qkv, float* __restrict__ out)
{
    extern __shared__ float sm[];
    float* Ks = sm;                    // 128*65
    float* Vs = sm + 128 * 65;         // 128*65
    float* Qs = sm + 2 * 128 * 65;     // 64*64

    const int tid = threadIdx.x;
    const int s0 = blockIdx.x * 64;
    const int h  = blockIdx.y;
    const int b  = blockIdx.z;

    // --- load K/V window (128 rows x 64 floats each) ---
    #pragma unroll
    for (int i = 0; i < 4; ++i) {
        int idx = tid + i * 512;            // 0..2047
        int row = idx >> 4;                 // 0..127
        int d4  = (idx & 15) << 2;          // 0..60
        int pos = s0 - 32 + row;
        float4 kv = make_float4(0.f, 0.f, 0.f, 0.f);
        float4 vv = kv;
        if (pos >= 0 && pos < SEQ) {
            const float* p = qkv + (size_t)(b * SEQ + pos) * (3 * DMODEL) + h * HDIM + d4;
            kv = *(const float4*)(p + DMODEL);       // k block
            vv = *(const float4*)(p + 2 * DMODEL);   // v block
        }
        float* kd = Ks + row * 65 + d4;
        kd[0] = kv.x; kd[1] = kv.y; kd[2] = kv.z; kd[3] = kv.w;
        float* vd = Vs + row * 65 + d4;
        vd[0] = vv.x; vd[1] = vv.y; vd[2] = vv.z; vd[3] = vv.w;
    }
    // --- load Q tile (64 rows x 64 floats) ---
    #pragma unroll
    for (int i = 0; i < 2; ++i) {
        int idx = tid + i * 512;            // 0..1023
        int qi  = idx >> 4;
        int d4  = (idx & 15) << 2;
        *(float4*)(Qs + qi * 64 + d4) =
            *(const float4*)(qkv + (size_t)(b * SEQ + s0 + qi) * (3 * DMODEL) + h * HDIM + d4);
    }
    __syncthreads();

    const int warp = tid >> 5;
    const int lane = tid & 31;
    const float scale = 0.125f;   // 1/sqrt(64)

    #pragma unroll 1
    for (int qq = 0; qq < 4; ++qq) {
        int qi = warp * 4 + qq;           // 0..63
        int sq = s0 + qi;                 // global query position
        const float* qr = Qs + qi * 64;

        // scores: lane owns window entries j = lane, lane+32, and (lane==0) 64
        float sA, sB, sC;
        {
            const float* krA = Ks + (qi + lane) * 65;
            const float* krB = Ks + (qi + lane + 32) * 65;
            float accA = 0.f, accB = 0.f;
            #pragma unroll
            for (int d = 0; d < 64; ++d) {
                float q = qr[d];
                accA = fmaf(q, krA[d], accA);
                accB = fmaf(q, krB[d], accB);
            }
            sA = accA * scale;
            sB = accB * scale;
            int posA = sq - 32 + lane;
            int posB = posA + 32;
            if (posA < 0 || posA >= SEQ) sA = -1e9f;
            if (posB < 0 || posB >= SEQ) sB = -1e9f;
        }
        sC = -1e9f;
        if (lane == 0) {
            int posC = sq + 32;
            if (posC >= 0 && posC < SEQ) {
                const float* krC = Ks + (qi + 64) * 65;
                float accC = 0.f;
                #pragma unroll
                for (int d = 0; d < 64; ++d) accC = fmaf(qr[d], krC[d], accC);
                sC = accC * scale;
            }
        }

        // softmax over 65 entries (warp reduction)
        float m = fmaxf(fmaxf(sA, sB), sC);
        #pragma unroll
        for (int o = 16; o > 0; o >>= 1)
            m = fmaxf(m, __shfl_xor_sync(0xffffffffu, m, o));

        float pA = expf(sA - m);
        float pB = expf(sB - m);
        float pC = expf(sC - m);
        float ssum = pA + pB + pC;
        #pragma unroll
        for (int o = 16; o > 0; o >>= 1)
            ssum += __shfl_xor_sync(0xffffffffu, ssum, o);
        float inv = 1.0f / ssum;

        // weighted sum of V: lane owns output dims d=lane and d=lane+32
        float a0 = 0.f, a1 = 0.f;
        #pragma unroll
        for (int jj = 0; jj < 65; ++jj) {
            float pv = (jj < 32) ? pA : ((jj < 64) ? pB : pC);
            pv = __shfl_sync(0xffffffffu, pv, jj & 31);
            const float* vr = Vs + (qi + jj) * 65;
            a0 = fmaf(pv, vr[lane], a0);
            a1 = fmaf(pv, vr[lane + 32], a1);
        }

        float* op = out + (size_t)(b * SEQ + sq) * DMODEL + h * HDIM;
        op[lane]      = a0 * inv;
        op[lane + 32] = a1 * inv;
    }
}

// ---------------------------------------------------------------------------
// Launch
// ---------------------------------------------------------------------------
extern "C" void kernel_launch(void* const* d_in, const int* in_sizes, int n_in,
                              void* d_out, int out_size)
{
    const float* x      = (const float*)d_in[0];   // [2,2048,512]
    const float* w_qkv  = (const float*)d_in[1];   // [512,1536]
    const float* b_qkv  = (const float*)d_in[2];   // [1536]
    const float* w_out  = (const float*)d_in[3];   // [512,512]
    const float* b_out  = (const float*)d_in[4];   // [512]
    float* out          = (float*)d_out;           // [2,2048,512]

    float* qkv_buf;
    float* attn_buf;
    cudaGetSymbolAddress((void**)&qkv_buf, g_qkv);
    cudaGetSymbolAddress((void**)&attn_buf, g_attn);

    const int M = BATCH * SEQ;     // 4096

    // GEMM1: qkv = x @ w_qkv + b_qkv   [4096 x 1536], K=512
    {
        dim3 grid((3 * DMODEL) / 128, M / 128);
        sgemm_bias_kernel<<<grid, 256>>>(x, w_qkv, b_qkv, qkv_buf, M, 3 * DMODEL, DMODEL);
    }

    // Sliding-window attention
    {
        int smem = ATT_SMEM_FLOATS * (int)sizeof(float);   // 82944 B
        cudaFuncSetAttribute(attn_window_kernel,
                             cudaFuncAttributeMaxDynamicSharedMemorySize, smem);
        dim3 grid(SEQ / 64, NHEAD, BATCH);
        attn_window_kernel<<<grid, 512, smem>>>(qkv_buf, attn_buf);
    }

    // GEMM2: out = attn @ w_out + b_out   [4096 x 512], K=512
    {
        dim3 grid(DMODEL / 128, M / 128);
        sgemm_bias_kernel<<<grid, 256>>>(attn_buf, w_out, b_out, out, M, DMODEL, DMODEL);
    }
}

// round 2
// speedup vs baseline: 1.2964x; 1.2964x over previous
#include <cuda_runtime.h>
#include <cuda_bf16.h>
#include <math.h>
#include <stdint.h>

// Problem constants
#define BATCH 2
#define SEQ   2048
#define DMODEL 512
#define NHEAD 8
#define HDIM  64
#define WIN   32
#define WFULL 65
#define MROWS (BATCH * SEQ)   // 4096

// ---------------------------------------------------------------------------
// Device-global scratch (no allocation allowed)
// ---------------------------------------------------------------------------
__device__ float g_qkv[BATCH * SEQ * 3 * DMODEL];                 // fp32 qkv
__device__ __nv_bfloat16 g_xh[MROWS * DMODEL];                    // x split
__device__ __nv_bfloat16 g_xl[MROWS * DMODEL];
__device__ __nv_bfloat16 g_w1h[3 * DMODEL * DMODEL];              // w_qkv^T [1536][512]
__device__ __nv_bfloat16 g_w1l[3 * DMODEL * DMODEL];
__device__ __nv_bfloat16 g_w2h[DMODEL * DMODEL];                  // w_out^T [512][512]
__device__ __nv_bfloat16 g_w2l[DMODEL * DMODEL];
__device__ __nv_bfloat16 g_ah[MROWS * DMODEL];                    // attn out split
__device__ __nv_bfloat16 g_al[MROWS * DMODEL];

// ---------------------------------------------------------------------------
// Elementwise fp32 -> bf16 (hi, lo) split, same layout
// ---------------------------------------------------------------------------
__global__ void conv_split_kernel(const float* __restrict__ in,
                                  __nv_bfloat16* __restrict__ h,
                                  __nv_bfloat16* __restrict__ l, int n4)
{
    int i = blockIdx.x * blockDim.x + threadIdx.x;
    if (i < n4) {
        float4 v = ((const float4*)in)[i];
        __nv_bfloat16 h0 = __float2bfloat16(v.x);
        __nv_bfloat16 h1 = __float2bfloat16(v.y);
        __nv_bfloat16 h2 = __float2bfloat16(v.z);
        __nv_bfloat16 h3 = __float2bfloat16(v.w);
        __nv_bfloat162 hh0 = {h0, h1}, hh1 = {h2, h3};
        ((__nv_bfloat162*)h)[i * 2 + 0] = hh0;
        ((__nv_bfloat162*)h)[i * 2 + 1] = hh1;
        __nv_bfloat162 ll0 = {__float2bfloat16(v.x - __bfloat162float(h0)),
                              __float2bfloat16(v.y - __bfloat162float(h1))};
        __nv_bfloat162 ll1 = {__float2bfloat16(v.z - __bfloat162float(h2)),
                              __float2bfloat16(v.w - __bfloat162float(h3))};
        ((__nv_bfloat162*)l)[i * 2 + 0] = ll0;
        ((__nv_bfloat162*)l)[i * 2 + 1] = ll1;
    }
}

// ---------------------------------------------------------------------------
// Transpose + split: in fp32 [K][N] -> out bf16 [N][K] (hi, lo)
// ---------------------------------------------------------------------------
__global__ void conv_splitT_kernel(const float* __restrict__ in,
                                   __nv_bfloat16* __restrict__ h,
                                   __nv_bfloat16* __restrict__ l,
                                   int K, int N)
{
    __shared__ float t[32][33];
    int k0 = blockIdx.y * 32, n0 = blockIdx.x * 32;
    int tx = threadIdx.x, ty = threadIdx.y;
    #pragma unroll
    for (int i = 0; i < 4; ++i)
        t[ty + i * 8][tx] = in[(size_t)(k0 + ty + i * 8) * N + n0 + tx];
    __syncthreads();
    #pragma unroll
    for (int i = 0; i < 4; ++i) {
        float v = t[tx][ty + i * 8];
        int n = n0 + ty + i * 8;
        int k = k0 + tx;
        __nv_bfloat16 hv = __float2bfloat16(v);
        h[(size_t)n * K + k] = hv;
        l[(size_t)n * K + k] = __float2bfloat16(v - __bfloat162float(hv));
    }
}

// ---------------------------------------------------------------------------
// Tensor-core GEMM, bf16 2-term split (3 products), fp32 accumulate.
// C[M,N] = A @ B^T + bias, where A given as (Ah+Al)[M][K] bf16 and
// B^T given as (Bh+Bl)[N][K] bf16. Tile 128x128x32, 256 threads, 8 warps
// (2x4), warp tile 64x32 of m16n8k16 mma.
// ---------------------------------------------------------------------------
#define GSTRIDE 48   // smem row stride in bf16 elements (96B, 16B-aligned)

__device__ __forceinline__ uint32_t smem_u32(const void* p) {
    return (uint32_t)__cvta_generic_to_shared(p);
}

__global__ __launch_bounds__(256) void bf16x3_gemm_kernel(
    const __nv_bfloat16* __restrict__ Ah, const __nv_bfloat16* __restrict__ Al,
    const __nv_bfloat16* __restrict__ Bh, const __nv_bfloat16* __restrict__ Bl,
    const float* __restrict__ bias, float* __restrict__ C,
    int M, int N, int K)
{
    extern __shared__ __nv_bfloat16 sm[];
    const int SA = 128 * GSTRIDE;
    __nv_bfloat16* sAh = sm;
    __nv_bfloat16* sAl = sm + SA;
    __nv_bfloat16* sBh = sm + 2 * SA;
    __nv_bfloat16* sBl = sm + 3 * SA;

    const int tid = threadIdx.x;
    const int warp = tid >> 5, lane = tid & 31;
    const int bm = blockIdx.y * 128, bn = blockIdx.x * 128;
    const int wm = (warp >> 2) * 64;    // 0 or 64
    const int wn = (warp & 3) * 32;     // 0,32,64,96

    // global-load mapping: 256 threads, each covers 16 bf16 of a 128x32 tile
    const int lrow = tid >> 1;              // 0..127
    const int lcol = (tid & 1) * 16;        // 0 or 16

    const __nv_bfloat16* gAh = Ah + (size_t)(bm + lrow) * K + lcol;
    const __nv_bfloat16* gAl = Al + (size_t)(bm + lrow) * K + lcol;
    const __nv_bfloat16* gBh = Bh + (size_t)(bn + lrow) * K + lcol;
    const __nv_bfloat16* gBl = Bl + (size_t)(bn + lrow) * K + lcol;

    float acc[4][4][4];
    #pragma unroll
    for (int i = 0; i < 4; ++i)
        #pragma unroll
        for (int j = 0; j < 4; ++j)
            #pragma unroll
            for (int r = 0; r < 4; ++r) acc[i][j][r] = 0.0f;

    const int nk = K >> 5;   // K/32

    // register prefetch of tile 0
    uint4 rAh0 = *(const uint4*)(gAh), rAh1 = *(const uint4*)(gAh + 8);
    uint4 rAl0 = *(const uint4*)(gAl), rAl1 = *(const uint4*)(gAl + 8);
    uint4 rBh0 = *(const uint4*)(gBh), rBh1 = *(const uint4*)(gBh + 8);
    uint4 rBl0 = *(const uint4*)(gBl), rBl1 = *(const uint4*)(gBl + 8);

    for (int t = 0; t < nk; ++t) {
        // commit staged registers to smem
        *(uint4*)&sAh[lrow * GSTRIDE + lcol] = rAh0;
        *(uint4*)&sAh[lrow * GSTRIDE + lcol + 8] = rAh1;
        *(uint4*)&sAl[lrow * GSTRIDE + lcol] = rAl0;
        *(uint4*)&sAl[lrow * GSTRIDE + lcol + 8] = rAl1;
        *(uint4*)&sBh[lrow * GSTRIDE + lcol] = rBh0;
        *(uint4*)&sBh[lrow * GSTRIDE + lcol + 8] = rBh1;
        *(uint4*)&sBl[lrow * GSTRIDE + lcol] = rBl0;
        *(uint4*)&sBl[lrow * GSTRIDE + lcol + 8] = rBl1;
        __syncthreads();

        if (t + 1 < nk) {
            int off = (t + 1) * 32;
            rAh0 = *(const uint4*)(gAh + off); rAh1 = *(const uint4*)(gAh + off + 8);
            rAl0 = *(const uint4*)(gAl + off); rAl1 = *(const uint4*)(gAl + off + 8);
            rBh0 = *(const uint4*)(gBh + off); rBh1 = *(const uint4*)(gBh + off + 8);
            rBl0 = *(const uint4*)(gBl + off); rBl1 = *(const uint4*)(gBl + off + 8);
        }

        #pragma unroll
        for (int ks = 0; ks < 32; ks += 16) {
            // B fragments for 4 n-tiles (hi and lo)
            uint32_t bh[4][2], bl[4][2];
            #pragma unroll
            for (int nt = 0; nt < 4; ++nt) {
                uint32_t ab = smem_u32(&sBh[(wn + nt * 8 + (lane & 7)) * GSTRIDE +
                                            ks + ((lane >> 3) & 1) * 8]);
                asm volatile("ldmatrix.sync.aligned.m8n8.x2.shared.b16 {%0,%1}, [%2];"
                             : "=r"(bh[nt][0]), "=r"(bh[nt][1]) : "r"(ab));
                uint32_t al_ = smem_u32(&sBl[(wn + nt * 8 + (lane & 7)) * GSTRIDE +
                                             ks + ((lane >> 3) & 1) * 8]);
                asm volatile("ldmatrix.sync.aligned.m8n8.x2.shared.b16 {%0,%1}, [%2];"
                             : "=r"(bl[nt][0]), "=r"(bl[nt][1]) : "r"(al_));
            }
            #pragma unroll
            for (int mt = 0; mt < 4; ++mt) {
                uint32_t afh[4], afl[4];
                uint32_t aa = smem_u32(&sAh[(wm + mt * 16 + (lane & 15)) * GSTRIDE +
                                            ks + (lane >> 4) * 8]);
                asm volatile("ldmatrix.sync.aligned.m8n8.x4.shared.b16 {%0,%1,%2,%3}, [%4];"
                             : "=r"(afh[0]), "=r"(afh[1]), "=r"(afh[2]), "=r"(afh[3])
                             : "r"(aa));
                uint32_t aa2 = smem_u32(&sAl[(wm + mt * 16 + (lane & 15)) * GSTRIDE +
                                             ks + (lane >> 4) * 8]);
                asm volatile("ldmatrix.sync.aligned.m8n8.x4.shared.b16 {%0,%1,%2,%3}, [%4];"
                             : "=r"(afl[0]), "=r"(afl[1]), "=r"(afl[2]), "=r"(afl[3])
                             : "r"(aa2));
                #pragma unroll
                for (int nt = 0; nt < 4; ++nt) {
                    float* c = acc[mt][nt];
                    asm volatile(
                        "mma.sync.aligned.m16n8k16.row.col.f32.bf16.bf16.f32 "
                        "{%0,%1,%2,%3},{%4,%5,%6,%7},{%8,%9},{%0,%1,%2,%3};"
                        : "+f"(c[0]), "+f"(c[1]), "+f"(c[2]), "+f"(c[3])
                        : "r"(afh[0]), "r"(afh[1]), "r"(afh[2]), "r"(afh[3]),
                          "r"(bh[nt][0]), "r"(bh[nt][1]));
                    asm volatile(
                        "mma.sync.aligned.m16n8k16.row.col.f32.bf16.bf16.f32 "
                        "{%0,%1,%2,%3},{%4,%5,%6,%7},{%8,%9},{%0,%1,%2,%3};"
                        : "+f"(c[0]), "+f"(c[1]), "+f"(c[2]), "+f"(c[3])
                        : "r"(afh[0]), "r"(afh[1]), "r"(afh[2]), "r"(afh[3]),
                          "r"(bl[nt][0]), "r"(bl[nt][1]));
                    asm volatile(
                        "mma.sync.aligned.m16n8k16.row.col.f32.bf16.bf16.f32 "
                        "{%0,%1,%2,%3},{%4,%5,%6,%7},{%8,%9},{%0,%1,%2,%3};"
                        : "+f"(c[0]), "+f"(c[1]), "+f"(c[2]), "+f"(c[3])
                        : "r"(afl[0]), "r"(afl[1]), "r"(afl[2]), "r"(afl[3]),
                          "r"(bh[nt][0]), "r"(bh[nt][1]));
                }
            }
        }
        __syncthreads();
    }

    // epilogue: bias + fp32 store (float2 per fragment row)
    #pragma unroll
    for (int mt = 0; mt < 4; ++mt) {
        #pragma unroll
        for (int nt = 0; nt < 4; ++nt) {
            int row = bm + wm + mt * 16 + (lane >> 2);
            int col = bn + wn + nt * 8 + (lane & 3) * 2;
            float bx = bias[col], by = bias[col + 1];
            float2 v0 = {acc[mt][nt][0] + bx, acc[mt][nt][1] + by};
            float2 v1 = {acc[mt][nt][2] + bx, acc[mt][nt][3] + by};
            *(float2*)(C + (size_t)row * N + col) = v0;
            *(float2*)(C + (size_t)(row + 8) * N + col) = v1;
        }
    }
}

// ---------------------------------------------------------------------------
// Sliding-window attention (fp32 compute), emits bf16 hi/lo split output.
// ---------------------------------------------------------------------------
#define ATT_SMEM_FLOATS (2 * 128 * 65 + 64 * 64)

__global__ __launch_bounds__(512) void attn_window_kernel(
    const float* __restrict__ qkv,
    __nv_bfloat16* __restrict__ out_h, __nv_bfloat16* __restrict__ out_l)
{
    extern __shared__ float smf[];
    float* Ks = smf;
    float* Vs = smf + 128 * 65;
    float* Qs = smf + 2 * 128 * 65;

    const int tid = threadIdx.x;
    const int s0 = blockIdx.x * 64;
    const int h  = blockIdx.y;
    const int b  = blockIdx.z;

    #pragma unroll
    for (int i = 0; i < 4; ++i) {
        int idx = tid + i * 512;
        int row = idx >> 4;
        int d4  = (idx & 15) << 2;
        int pos = s0 - 32 + row;
        float4 kv = make_float4(0.f, 0.f, 0.f, 0.f);
        float4 vv = kv;
        if (pos >= 0 && pos < SEQ) {
            const float* p = qkv + (size_t)(b * SEQ + pos) * (3 * DMODEL) + h * HDIM + d4;
            kv = *(const float4*)(p + DMODEL);
            vv = *(const float4*)(p + 2 * DMODEL);
        }
        float* kd = Ks + row * 65 + d4;
        kd[0] = kv.x; kd[1] = kv.y; kd[2] = kv.z; kd[3] = kv.w;
        float* vd = Vs + row * 65 + d4;
        vd[0] = vv.x; vd[1] = vv.y; vd[2] = vv.z; vd[3] = vv.w;
    }
    #pragma unroll
    for (int i = 0; i < 2; ++i) {
        int idx = tid + i * 512;
        int qi  = idx >> 4;
        int d4  = (idx & 15) << 2;
        *(float4*)(Qs + qi * 64 + d4) =
            *(const float4*)(qkv + (size_t)(b * SEQ + s0 + qi) * (3 * DMODEL) + h * HDIM + d4);
    }
    __syncthreads();

    const int warp = tid >> 5;
    const int lane = tid & 31;
    const float scale = 0.125f;

    #pragma unroll 1
    for (int qq = 0; qq < 4; ++qq) {
        int qi = warp * 4 + qq;
        int sq = s0 + qi;
        const float* qr = Qs + qi * 64;

        float sA, sB, sC;
        {
            const float* krA = Ks + (qi + lane) * 65;
            const float* krB = Ks + (qi + lane + 32) * 65;
            float accA = 0.f, accB = 0.f;
            #pragma unroll
            for (int d = 0; d < 64; ++d) {
                float q = qr[d];
                accA = fmaf(q, krA[d], accA);
                accB = fmaf(q, krB[d], accB);
            }
            sA = accA * scale;
            sB = accB * scale;
            int posA = sq - 32 + lane;
            int posB = posA + 32;
            if (posA < 0 || posA >= SEQ) sA = -1e9f;
            if (posB < 0 || posB >= SEQ) sB = -1e9f;
        }
        sC = -1e9f;
        if (lane == 0) {
            int posC = sq + 32;
            if (posC >= 0 && posC < SEQ) {
                const float* krC = Ks + (qi + 64) * 65;
                float accC = 0.f;
                #pragma unroll
                for (int d = 0; d < 64; ++d) accC = fmaf(qr[d], krC[d], accC);
                sC = accC * scale;
            }
        }

        float m = fmaxf(fmaxf(sA, sB), sC);
        #pragma unroll
        for (int o = 16; o > 0; o >>= 1)
            m = fmaxf(m, __shfl_xor_sync(0xffffffffu, m, o));

        float pA = expf(sA - m);
        float pB = expf(sB - m);
        float pC = expf(sC - m);
        float ssum = pA + pB + pC;
        #pragma unroll
        for (int o = 16; o > 0; o >>= 1)
            ssum += __shfl_xor_sync(0xffffffffu, ssum, o);
        float inv = 1.0f / ssum;

        float a0 = 0.f, a1 = 0.f;
        #pragma unroll
        for (int jj = 0; jj < 65; ++jj) {
            float pv = (jj < 32) ? pA : ((jj < 64) ? pB : pC);
            pv = __shfl_sync(0xffffffffu, pv, jj & 31);
            const float* vr = Vs + (qi + jj) * 65;
            a0 = fmaf(pv, vr[lane], a0);
            a1 = fmaf(pv, vr[lane + 32], a1);
        }

        float v0 = a0 * inv, v1 = a1 * inv;
        size_t base = (size_t)(b * SEQ + sq) * DMODEL + h * HDIM;
        __nv_bfloat16 h0 = __float2bfloat16(v0);
        __nv_bfloat16 h1 = __float2bfloat16(v1);
        out_h[base + lane]      = h0;
        out_h[base + lane + 32] = h1;
        out_l[base + lane]      = __float2bfloat16(v0 - __bfloat162float(h0));
        out_l[base + lane + 32] = __float2bfloat16(v1 - __bfloat162float(h1));
    }
}

// ---------------------------------------------------------------------------
// Launch
// ---------------------------------------------------------------------------
extern "C" void kernel_launch(void* const* d_in, const int* in_sizes, int n_in,
                              void* d_out, int out_size)
{
    const float* x      = (const float*)d_in[0];
    const float* w_qkv  = (const float*)d_in[1];
    const float* b_qkv  = (const float*)d_in[2];
    const float* w_out  = (const float*)d_in[3];
    const float* b_out  = (const float*)d_in[4];
    float* out          = (float*)d_out;

    float *qkv_buf;
    __nv_bfloat16 *xh, *xl, *w1h, *w1l, *w2h, *w2l, *ah, *al;
    cudaGetSymbolAddress((void**)&qkv_buf, g_qkv);
    cudaGetSymbolAddress((void**)&xh, g_xh);
    cudaGetSymbolAddress((void**)&xl, g_xl);
    cudaGetSymbolAddress((void**)&w1h, g_w1h);
    cudaGetSymbolAddress((void**)&w1l, g_w1l);
    cudaGetSymbolAddress((void**)&w2h, g_w2h);
    cudaGetSymbolAddress((void**)&w2l, g_w2l);
    cudaGetSymbolAddress((void**)&ah, g_ah);
    cudaGetSymbolAddress((void**)&al, g_al);

    const int M = MROWS;   // 4096

    // split x
    {
        int n4 = (M * DMODEL) / 4;
        conv_split_kernel<<<(n4 + 255) / 256, 256>>>(x, xh, xl, n4);
    }
    // transpose+split weights
    {
        dim3 blk(32, 8);
        conv_splitT_kernel<<<dim3((3 * DMODEL) / 32, DMODEL / 32), blk>>>(w_qkv, w1h, w1l, DMODEL, 3 * DMODEL);
        conv_splitT_kernel<<<dim3(DMODEL / 32, DMODEL / 32), blk>>>(w_out, w2h, w2l, DMODEL, DMODEL);
    }

    const int gemm_smem = 4 * 128 * GSTRIDE * (int)sizeof(__nv_bfloat16);  // 49152
    cudaFuncSetAttribute(bf16x3_gemm_kernel,
                         cudaFuncAttributeMaxDynamicSharedMemorySize, gemm_smem);

    // GEMM1: qkv = x @ w_qkv + b_qkv  [4096 x 1536], K=512
    {
        dim3 grid((3 * DMODEL) / 128, M / 128);
        bf16x3_gemm_kernel<<<grid, 256, gemm_smem>>>(xh, xl, w1h, w1l, b_qkv,
                                                     qkv_buf, M, 3 * DMODEL, DMODEL);
    }

    // attention
    {
        int smem = ATT_SMEM_FLOATS * (int)sizeof(float);
        cudaFuncSetAttribute(attn_window_kernel,
                             cudaFuncAttributeMaxDynamicSharedMemorySize, smem);
        dim3 grid(SEQ / 64, NHEAD, BATCH);
        attn_window_kernel<<<grid, 512, smem>>>(qkv_buf, ah, al);
    }

    // GEMM2: out = attn @ w_out + b_out  [4096 x 512], K=512
    {
        dim3 grid(DMODEL / 128, M / 128);
        bf16x3_gemm_kernel<<<grid, 256, gemm_smem>>>(ah, al, w2h, w2l, b_out,
                                                     out, M, DMODEL, DMODEL);
    }
}

// round 6
// speedup vs baseline: 1.6684x; 1.2870x over previous
#include <cuda_runtime.h>
#include <cuda_bf16.h>
#include <math.h>
#include <stdint.h>

#define BATCH 2
#define SEQ   2048
#define DMODEL 512
#define NHEAD 8
#define HDIM  64
#define MROWS (BATCH * SEQ)   // 4096

typedef __nv_bfloat16 bf16;
typedef __nv_bfloat162 bf162;

// ---------------------------------------------------------------------------
// Device-global scratch
// ---------------------------------------------------------------------------
__device__ bf16 g_xh[MROWS * DMODEL];
__device__ bf16 g_xl[MROWS * DMODEL];
__device__ bf16 g_w1h[3 * DMODEL * DMODEL];
__device__ bf16 g_w1l[3 * DMODEL * DMODEL];
__device__ bf16 g_w2h[DMODEL * DMODEL];
__device__ bf16 g_w2l[DMODEL * DMODEL];
__device__ bf16 g_qkvh[MROWS * 3 * DMODEL];
__device__ bf16 g_qkvl[MROWS * 3 * DMODEL];
__device__ bf16 g_ah[MROWS * DMODEL];
__device__ bf16 g_al[MROWS * DMODEL];

__device__ __forceinline__ uint32_t smem_u32(const void* p) {
    return (uint32_t)__cvta_generic_to_shared(p);
}
__device__ __forceinline__ uint32_t pack2(float a, float b) {
    bf162 t;
    t.x = __float2bfloat16(a);
    t.y = __float2bfloat16(b);
    return *(uint32_t*)&t;
}

#define MMA_BF16(c, a, b)                                                      \
    asm volatile(                                                              \
        "mma.sync.aligned.m16n8k16.row.col.f32.bf16.bf16.f32 "                 \
        "{%0,%1,%2,%3},{%4,%5,%6,%7},{%8,%9},{%0,%1,%2,%3};"                   \
        : "+f"((c)[0]), "+f"((c)[1]), "+f"((c)[2]), "+f"((c)[3])               \
        : "r"((a)[0]), "r"((a)[1]), "r"((a)[2]), "r"((a)[3]),                  \
          "r"((b)[0]), "r"((b)[1]))

#define LDSM_X4(r, addr)                                                       \
    asm volatile("ldmatrix.sync.aligned.m8n8.x4.shared.b16 {%0,%1,%2,%3}, [%4];" \
                 : "=r"((r)[0]), "=r"((r)[1]), "=r"((r)[2]), "=r"((r)[3])      \
                 : "r"(addr))

#define LDSM_X2(r, addr)                                                       \
    asm volatile("ldmatrix.sync.aligned.m8n8.x2.shared.b16 {%0,%1}, [%2];"     \
                 : "=r"((r)[0]), "=r"((r)[1]) : "r"(addr))

#define CP_ASYNC16(dst, src)                                                   \
    asm volatile("cp.async.cg.shared.global [%0], [%1], 16;" ::"r"(dst), "l"(src))

// ---------------------------------------------------------------------------
// fp32 -> bf16 hi/lo split (elementwise)
// ---------------------------------------------------------------------------
__global__ void conv_split_kernel(const float* __restrict__ in,
                                  bf16* __restrict__ h, bf16* __restrict__ l,
                                  int n4)
{
    int i = blockIdx.x * blockDim.x + threadIdx.x;
    if (i < n4) {
        float4 v = ((const float4*)in)[i];
        bf16 h0 = __float2bfloat16(v.x), h1 = __float2bfloat16(v.y);
        bf16 h2 = __float2bfloat16(v.z), h3 = __float2bfloat16(v.w);
        bf162 hh0 = {h0, h1}, hh1 = {h2, h3};
        ((bf162*)h)[i * 2 + 0] = hh0;
        ((bf162*)h)[i * 2 + 1] = hh1;
        bf162 ll0 = {__float2bfloat16(v.x - __bfloat162float(h0)),
                     __float2bfloat16(v.y - __bfloat162float(h1))};
        bf162 ll1 = {__float2bfloat16(v.z - __bfloat162float(h2)),
                     __float2bfloat16(v.w - __bfloat162float(h3))};
        ((bf162*)l)[i * 2 + 0] = ll0;
        ((bf162*)l)[i * 2 + 1] = ll1;
    }
}

// Transpose + split: fp32 [K][N] -> bf16 [N][K] hi/lo
__global__ void conv_splitT_kernel(const float* __restrict__ in,
                                   bf16* __restrict__ h, bf16* __restrict__ l,
                                   int K, int N)
{
    __shared__ float t[32][33];
    int k0 = blockIdx.y * 32, n0 = blockIdx.x * 32;
    int tx = threadIdx.x, ty = threadIdx.y;
    #pragma unroll
    for (int i = 0; i < 4; ++i)
        t[ty + i * 8][tx] = in[(size_t)(k0 + ty + i * 8) * N + n0 + tx];
    __syncthreads();
    #pragma unroll
    for (int i = 0; i < 4; ++i) {
        float v = t[tx][ty + i * 8];
        int n = n0 + ty + i * 8;
        int k = k0 + tx;
        bf16 hv = __float2bfloat16(v);
        h[(size_t)n * K + k] = hv;
        l[(size_t)n * K + k] = __float2bfloat16(v - __bfloat162float(hv));
    }
}

// ---------------------------------------------------------------------------
// Tensor-core GEMM, bf16 2-term split (3 products), cp.async double-buffer.
// Tile 128x128x32, 256 threads, smem stride 40 (conflict-free ldmatrix).
// OUTBF16=1: emit bf16 hi/lo split; else fp32.
// ---------------------------------------------------------------------------
#define GS 40
#define STG_ELEMS (4 * 128 * GS)   // elems per stage (Ah,Al,Bh,Bl)

template <int OUTBF16>
__global__ __launch_bounds__(256) void gemm_tc(
    const bf16* __restrict__ Ah, const bf16* __restrict__ Al,
    const bf16* __restrict__ Bh, const bf16* __restrict__ Bl,
    const float* __restrict__ bias,
    float* __restrict__ Cf, bf16* __restrict__ Ch, bf16* __restrict__ Cl,
    int M, int N, int K)
{
    extern __shared__ bf16 sm[];

    const int tid = threadIdx.x;
    const int warp = tid >> 5, lane = tid & 31;
    const int bm = blockIdx.y * 128, bn = blockIdx.x * 128;
    const int wm = (warp >> 2) * 64, wn = (warp & 3) * 32;
    const int lrow = tid >> 1, lcol = (tid & 1) * 16;

    const bf16* gsrc[4];
    gsrc[0] = Ah + (size_t)(bm + lrow) * K + lcol;
    gsrc[1] = Al + (size_t)(bm + lrow) * K + lcol;
    gsrc[2] = Bh + (size_t)(bn + lrow) * K + lcol;
    gsrc[3] = Bl + (size_t)(bn + lrow) * K + lcol;

    uint32_t sdst0[4];
    #pragma unroll
    for (int q = 0; q < 4; ++q)
        sdst0[q] = smem_u32(sm + q * 128 * GS + lrow * GS + lcol);

    float acc[4][4][4];
    #pragma unroll
    for (int i = 0; i < 4; ++i)
        #pragma unroll
        for (int j = 0; j < 4; ++j)
            #pragma unroll
            for (int r = 0; r < 4; ++r) acc[i][j][r] = 0.0f;

    const int nk = K >> 5;

    // stage 0  (each thread: 16 elems = two 16B chunks at +0 and +16 BYTES)
    #pragma unroll
    for (int q = 0; q < 4; ++q) {
        CP_ASYNC16(sdst0[q], gsrc[q]);
        CP_ASYNC16(sdst0[q] + 16, gsrc[q] + 8);
    }
    asm volatile("cp.async.commit_group;");
    asm volatile("cp.async.wait_group 0;");
    __syncthreads();

    for (int t = 0; t < nk; ++t) {
        if (t + 1 < nk) {
            uint32_t so = ((t + 1) & 1) * (STG_ELEMS * 2);   // byte offset of stage
            int off = (t + 1) * 32;
            #pragma unroll
            for (int q = 0; q < 4; ++q) {
                CP_ASYNC16(sdst0[q] + so, gsrc[q] + off);
                CP_ASYNC16(sdst0[q] + so + 16, gsrc[q] + off + 8);
            }
            asm volatile("cp.async.commit_group;");
        }

        const bf16* base = sm + (t & 1) * STG_ELEMS;
        const bf16* sAh = base;
        const bf16* sAl = base + 128 * GS;
        const bf16* sBh = base + 2 * 128 * GS;
        const bf16* sBl = base + 3 * 128 * GS;

        #pragma unroll
        for (int ks = 0; ks < 32; ks += 16) {
            uint32_t bh[4][2], bl[4][2];
            #pragma unroll
            for (int nt = 0; nt < 4; ++nt) {
                uint32_t ab = smem_u32(&sBh[(wn + nt * 8 + (lane & 7)) * GS +
                                            ks + ((lane >> 3) & 1) * 8]);
                LDSM_X2(bh[nt], ab);
                uint32_t ab2 = smem_u32(&sBl[(wn + nt * 8 + (lane & 7)) * GS +
                                             ks + ((lane >> 3) & 1) * 8]);
                LDSM_X2(bl[nt], ab2);
            }
            #pragma unroll
            for (int mt = 0; mt < 4; ++mt) {
                uint32_t afh[4], afl[4];
                uint32_t aa = smem_u32(&sAh[(wm + mt * 16 + (lane & 15)) * GS +
                                            ks + (lane >> 4) * 8]);
                LDSM_X4(afh, aa);
                uint32_t aa2 = smem_u32(&sAl[(wm + mt * 16 + (lane & 15)) * GS +
                                             ks + (lane >> 4) * 8]);
                LDSM_X4(afl, aa2);
                #pragma unroll
                for (int nt = 0; nt < 4; ++nt) {
                    MMA_BF16(acc[mt][nt], afh, bh[nt]);
                    MMA_BF16(acc[mt][nt], afh, bl[nt]);
                    MMA_BF16(acc[mt][nt], afl, bh[nt]);
                }
            }
        }
        asm volatile("cp.async.wait_group 0;");
        __syncthreads();
    }

    #pragma unroll
    for (int mt = 0; mt < 4; ++mt) {
        #pragma unroll
        for (int nt = 0; nt < 4; ++nt) {
            int row = bm + wm + mt * 16 + (lane >> 2);
            int col = bn + wn + nt * 8 + (lane & 3) * 2;
            float bx = bias[col], by = bias[col + 1];
            float v0 = acc[mt][nt][0] + bx, v1 = acc[mt][nt][1] + by;
            float v2 = acc[mt][nt][2] + bx, v3 = acc[mt][nt][3] + by;
            if (OUTBF16) {
                bf162 hh0; hh0.x = __float2bfloat16(v0); hh0.y = __float2bfloat16(v1);
                *(uint32_t*)(Ch + (size_t)row * N + col) = *(uint32_t*)&hh0;
                bf162 ll0 = {__float2bfloat16(v0 - __bfloat162float(hh0.x)),
                             __float2bfloat16(v1 - __bfloat162float(hh0.y))};
                *(uint32_t*)(Cl + (size_t)row * N + col) = *(uint32_t*)&ll0;
                bf162 hh1; hh1.x = __float2bfloat16(v2); hh1.y = __float2bfloat16(v3);
                *(uint32_t*)(Ch + (size_t)(row + 8) * N + col) = *(uint32_t*)&hh1;
                bf162 ll1 = {__float2bfloat16(v2 - __bfloat162float(hh1.x)),
                             __float2bfloat16(v3 - __bfloat162float(hh1.y))};
                *(uint32_t*)(Cl + (size_t)(row + 8) * N + col) = *(uint32_t*)&ll1;
            } else {
                float2 f0 = {v0, v1}, f1 = {v2, v3};
                *(float2*)(Cf + (size_t)row * N + col) = f0;
                *(float2*)(Cf + (size_t)(row + 8) * N + col) = f1;
            }
        }
    }
}

// ---------------------------------------------------------------------------
// Tensor-core sliding-window attention.
// CTA = (b, h, 64 queries), 128 threads = 4 warps, warp = 16 queries.
// S[16 x 128] = Q * K^T (bf16 3-product split), mask+softmax in registers,
// O[16 x 64] = P * V with P re-packed to A-fragments in registers.
// Emits bf16 hi/lo for the output projection.
// ---------------------------------------------------------------------------
#define A_KH 0
#define A_KL (128 * 72)
#define A_VTH (2 * 128 * 72)
#define A_VTL (2 * 128 * 72 + 64 * 136)
#define A_QH (2 * 128 * 72 + 2 * 64 * 136)
#define A_QL (2 * 128 * 72 + 2 * 64 * 136 + 64 * 72)
#define A_SMEM_ELEMS (2 * 128 * 72 + 2 * 64 * 136 + 2 * 64 * 72)   // 45056

__global__ __launch_bounds__(128) void attn_tc_kernel(
    const bf16* __restrict__ qkvh, const bf16* __restrict__ qkvl,
    bf16* __restrict__ outh, bf16* __restrict__ outl)
{
    extern __shared__ bf16 sm[];

    const int tid = threadIdx.x;
    const int warp = tid >> 5, lane = tid & 31;
    const int s0 = blockIdx.x * 64;
    const int h = blockIdx.y;
    const int b = blockIdx.z;

    // ---- load K rows + transposed V (window rows s0-32 .. s0+95) ----
    {
        int pos = s0 - 32 + tid;
        uint4* dkh = (uint4*)(sm + A_KH + tid * 72);
        uint4* dkl = (uint4*)(sm + A_KL + tid * 72);
        if (pos >= 0 && pos < SEQ) {
            size_t rowb = (size_t)(b * SEQ + pos) * (3 * DMODEL);
            const uint4* kh = (const uint4*)(qkvh + rowb + DMODEL + h * HDIM);
            const uint4* kl = (const uint4*)(qkvl + rowb + DMODEL + h * HDIM);
            #pragma unroll
            for (int i = 0; i < 8; ++i) { dkh[i] = kh[i]; dkl[i] = kl[i]; }
            const uint32_t* vh = (const uint32_t*)(qkvh + rowb + 2 * DMODEL + h * HDIM);
            const uint32_t* vl = (const uint32_t*)(qkvl + rowb + 2 * DMODEL + h * HDIM);
            #pragma unroll
            for (int i = 0; i < 32; ++i) {
                uint32_t ph = vh[i], pl = vl[i];
                bf162 th = *(bf162*)&ph, tl = *(bf162*)&pl;
                sm[A_VTH + (2 * i) * 136 + tid] = th.x;
                sm[A_VTH + (2 * i + 1) * 136 + tid] = th.y;
                sm[A_VTL + (2 * i) * 136 + tid] = tl.x;
                sm[A_VTL + (2 * i + 1) * 136 + tid] = tl.y;
            }
        } else {
            uint4 z = {0, 0, 0, 0};
            #pragma unroll
            for (int i = 0; i < 8; ++i) { dkh[i] = z; dkl[i] = z; }
            bf16 zb = __float2bfloat16(0.0f);
            #pragma unroll
            for (int d = 0; d < 64; ++d) {
                sm[A_VTH + d * 136 + tid] = zb;
                sm[A_VTL + d * 136 + tid] = zb;
            }
        }
        // Q: 2 threads per row, 32 dims each
        int qr = tid >> 1, qo = (tid & 1) * 32;
        size_t rq = (size_t)(b * SEQ + s0 + qr) * (3 * DMODEL) + h * HDIM + qo;
        const uint4* qh = (const uint4*)(qkvh + rq);
        const uint4* ql = (const uint4*)(qkvl + rq);
        uint4* dqh = (uint4*)(sm + A_QH + qr * 72 + qo);
        uint4* dql = (uint4*)(sm + A_QL + qr * 72 + qo);
        #pragma unroll
        for (int i = 0; i < 4; ++i) { dqh[i] = qh[i]; dql[i] = ql[i]; }
    }
    __syncthreads();

    // ---- S = Q K^T ----
    float s[16][4];
    #pragma unroll
    for (int nt = 0; nt < 16; ++nt)
        #pragma unroll
        for (int j = 0; j < 4; ++j) s[nt][j] = 0.0f;

    const int qrow = warp * 16 + (lane & 15);
    #pragma unroll
    for (int kk = 0; kk < 4; ++kk) {
        uint32_t ah[4], al[4];
        uint32_t aa = smem_u32(sm + A_QH + qrow * 72 + kk * 16 + (lane >> 4) * 8);
        LDSM_X4(ah, aa);
        uint32_t aa2 = smem_u32(sm + A_QL + qrow * 72 + kk * 16 + (lane >> 4) * 8);
        LDSM_X4(al, aa2);
        #pragma unroll
        for (int nt = 0; nt < 16; ++nt) {
            uint32_t bh[2], bl[2];
            uint32_t ba = smem_u32(sm + A_KH + (nt * 8 + (lane & 7)) * 72 +
                                   kk * 16 + ((lane >> 3) & 1) * 8);
            LDSM_X2(bh, ba);
            uint32_t ba2 = smem_u32(sm + A_KL + (nt * 8 + (lane & 7)) * 72 +
                                    kk * 16 + ((lane >> 3) & 1) * 8);
            LDSM_X2(bl, ba2);
            MMA_BF16(s[nt], ah, bh);
            MMA_BF16(s[nt], ah, bl);
            MMA_BF16(s[nt], al, bh);
        }
    }

    // ---- scale + mask + softmax ----
    const int m0 = warp * 16 + (lane >> 2);
    const int m1 = m0 + 8;
    float mx0 = -1e30f, mx1 = -1e30f;
    #pragma unroll
    for (int nt = 0; nt < 16; ++nt) {
        #pragma unroll
        for (int jj = 0; jj < 2; ++jj) {
            int nn = nt * 8 + (lane & 3) * 2 + jj;
            int gpos = s0 - 32 + nn;
            bool vp = (gpos >= 0) && (gpos < SEQ);
            int d0 = nn - m0;
            s[nt][jj] = (vp && d0 >= 0 && d0 <= 64) ? s[nt][jj] * 0.125f : -1e9f;
            int d1 = nn - m1;
            s[nt][2 + jj] = (vp && d1 >= 0 && d1 <= 64) ? s[nt][2 + jj] * 0.125f : -1e9f;
        }
        mx0 = fmaxf(mx0, fmaxf(s[nt][0], s[nt][1]));
        mx1 = fmaxf(mx1, fmaxf(s[nt][2], s[nt][3]));
    }
    mx0 = fmaxf(mx0, __shfl_xor_sync(0xffffffffu, mx0, 1));
    mx0 = fmaxf(mx0, __shfl_xor_sync(0xffffffffu, mx0, 2));
    mx1 = fmaxf(mx1, __shfl_xor_sync(0xffffffffu, mx1, 1));
    mx1 = fmaxf(mx1, __shfl_xor_sync(0xffffffffu, mx1, 2));

    float sum0 = 0.f, sum1 = 0.f;
    #pragma unroll
    for (int nt = 0; nt < 16; ++nt) {
        s[nt][0] = __expf(s[nt][0] - mx0); sum0 += s[nt][0];
        s[nt][1] = __expf(s[nt][1] - mx0); sum0 += s[nt][1];
        s[nt][2] = __expf(s[nt][2] - mx1); sum1 += s[nt][2];
        s[nt][3] = __expf(s[nt][3] - mx1); sum1 += s[nt][3];
    }
    sum0 += __shfl_xor_sync(0xffffffffu, sum0, 1);
    sum0 += __shfl_xor_sync(0xffffffffu, sum0, 2);
    sum1 += __shfl_xor_sync(0xffffffffu, sum1, 1);
    sum1 += __shfl_xor_sync(0xffffffffu, sum1, 2);
    float inv0 = 1.0f / sum0, inv1 = 1.0f / sum1;

    // ---- O = P V  (P re-packed from registers into A fragments) ----
    float o[8][4];
    #pragma unroll
    for (int nt = 0; nt < 8; ++nt)
        #pragma unroll
        for (int j = 0; j < 4; ++j) o[nt][j] = 0.0f;

    #pragma unroll
    for (int kt = 0; kt < 8; ++kt) {
        float* pa = s[2 * kt];
        float* pb = s[2 * kt + 1];
        uint32_t ah[4], al[4];
        ah[0] = pack2(pa[0], pa[1]);
        ah[1] = pack2(pa[2], pa[3]);
        ah[2] = pack2(pb[0], pb[1]);
        ah[3] = pack2(pb[2], pb[3]);
        {
            bf162 t0 = *(bf162*)&ah[0], t1 = *(bf162*)&ah[1];
            bf162 t2 = *(bf162*)&ah[2], t3 = *(bf162*)&ah[3];
            al[0] = pack2(pa[0] - __bfloat162float(t0.x), pa[1] - __bfloat162float(t0.y));
            al[1] = pack2(pa[2] - __bfloat162float(t1.x), pa[3] - __bfloat162float(t1.y));
            al[2] = pack2(pb[0] - __bfloat162float(t2.x), pb[1] - __bfloat162float(t2.y));
            al[3] = pack2(pb[2] - __bfloat162float(t3.x), pb[3] - __bfloat162float(t3.y));
        }
        #pragma unroll
        for (int nt2 = 0; nt2 < 8; ++nt2) {
            uint32_t bh[2], bl[2];
            uint32_t ba = smem_u32(sm + A_VTH + (nt2 * 8 + (lane & 7)) * 136 +
                                   kt * 16 + ((lane >> 3) & 1) * 8);
            LDSM_X2(bh, ba);
            uint32_t ba2 = smem_u32(sm + A_VTL + (nt2 * 8 + (lane & 7)) * 136 +
                                    kt * 16 + ((lane >> 3) & 1) * 8);
            LDSM_X2(bl, ba2);
            MMA_BF16(o[nt2], ah, bh);
            MMA_BF16(o[nt2], ah, bl);
            MMA_BF16(o[nt2], al, bh);
        }
    }

    // ---- normalize + emit bf16 hi/lo ----
    size_t r0 = (size_t)(b * SEQ + s0 + m0) * DMODEL + h * HDIM;
    size_t r1 = r0 + (size_t)8 * DMODEL;
    #pragma unroll
    for (int nt2 = 0; nt2 < 8; ++nt2) {
        int d = nt2 * 8 + (lane & 3) * 2;
        float v0 = o[nt2][0] * inv0, v1 = o[nt2][1] * inv0;
        float v2 = o[nt2][2] * inv1, v3 = o[nt2][3] * inv1;
        uint32_t hh0 = pack2(v0, v1);
        bf162 th0 = *(bf162*)&hh0;
        *(uint32_t*)(outh + r0 + d) = hh0;
        *(uint32_t*)(outl + r0 + d) =
            pack2(v0 - __bfloat162float(th0.x), v1 - __bfloat162float(th0.y));
        uint32_t hh1 = pack2(v2, v3);
        bf162 th1 = *(bf162*)&hh1;
        *(uint32_t*)(outh + r1 + d) = hh1;
        *(uint32_t*)(outl + r1 + d) =
            pack2(v2 - __bfloat162float(th1.x), v3 - __bfloat162float(th1.y));
    }
}

// ---------------------------------------------------------------------------
// Launch
// ---------------------------------------------------------------------------
extern "C" void kernel_launch(void* const* d_in, const int* in_sizes, int n_in,
                              void* d_out, int out_size)
{
    const float* x     = (const float*)d_in[0];
    const float* w_qkv = (const float*)d_in[1];
    const float* b_qkv = (const float*)d_in[2];
    const float* w_out = (const float*)d_in[3];
    const float* b_out = (const float*)d_in[4];
    float* out         = (float*)d_out;

    bf16 *xh, *xl, *w1h, *w1l, *w2h, *w2l, *qh, *ql, *ah, *al;
    cudaGetSymbolAddress((void**)&xh, g_xh);
    cudaGetSymbolAddress((void**)&xl, g_xl);
    cudaGetSymbolAddress((void**)&w1h, g_w1h);
    cudaGetSymbolAddress((void**)&w1l, g_w1l);
    cudaGetSymbolAddress((void**)&w2h, g_w2h);
    cudaGetSymbolAddress((void**)&w2l, g_w2l);
    cudaGetSymbolAddress((void**)&qh, g_qkvh);
    cudaGetSymbolAddress((void**)&ql, g_qkvl);
    cudaGetSymbolAddress((void**)&ah, g_ah);
    cudaGetSymbolAddress((void**)&al, g_al);

    const int M = MROWS;

    {
        int n4 = (M * DMODEL) / 4;
        conv_split_kernel<<<(n4 + 255) / 256, 256>>>(x, xh, xl, n4);
    }
    {
        dim3 blk(32, 8);
        conv_splitT_kernel<<<dim3((3 * DMODEL) / 32, DMODEL / 32), blk>>>(
            w_qkv, w1h, w1l, DMODEL, 3 * DMODEL);
        conv_splitT_kernel<<<dim3(DMODEL / 32, DMODEL / 32), blk>>>(
            w_out, w2h, w2l, DMODEL, DMODEL);
    }

    const int gemm_smem = 2 * STG_ELEMS * (int)sizeof(bf16);   // 81920
    cudaFuncSetAttribute(gemm_tc<1>, cudaFuncAttributeMaxDynamicSharedMemorySize, gemm_smem);
    cudaFuncSetAttribute(gemm_tc<0>, cudaFuncAttributeMaxDynamicSharedMemorySize, gemm_smem);

    // GEMM1: qkv (bf16 hi/lo) = x @ w_qkv + b_qkv
    {
        dim3 grid((3 * DMODEL) / 128, M / 128);
        gemm_tc<1><<<grid, 256, gemm_smem>>>(xh, xl, w1h, w1l, b_qkv,
                                             nullptr, qh, ql, M, 3 * DMODEL, DMODEL);
    }

    // attention (tensor core)
    {
        int smem = A_SMEM_ELEMS * (int)sizeof(bf16);   // 90112
        cudaFuncSetAttribute(attn_tc_kernel,
                             cudaFuncAttributeMaxDynamicSharedMemorySize, smem);
        dim3 grid(SEQ / 64, NHEAD, BATCH);
        attn_tc_kernel<<<grid, 128, smem>>>(qh, ql, ah, al);
    }

    // GEMM2: out (fp32) = attn @ w_out + b_out
    {
        dim3 grid(DMODEL / 128, M / 128);
        gemm_tc<0><<<grid, 256, gemm_smem>>>(ah, al, w2h, w2l, b_out,
                                             out, nullptr, nullptr, M, DMODEL, DMODEL);
    }
}

// round 7
// speedup vs baseline: 1.8148x; 1.0877x over previous
#include <cuda_runtime.h>
#include <cuda_bf16.h>
#include <math.h>
#include <stdint.h>

#define BATCH 2
#define SEQ   2048
#define DMODEL 512
#define NHEAD 8
#define HDIM  64
#define MROWS (BATCH * SEQ)   // 4096

typedef __nv_bfloat16 bf16;
typedef __nv_bfloat162 bf162;

// ---------------------------------------------------------------------------
// Device-global scratch
// ---------------------------------------------------------------------------
__device__ bf16 g_xh[MROWS * DMODEL];
__device__ bf16 g_xl[MROWS * DMODEL];
__device__ bf16 g_w1h[3 * DMODEL * DMODEL];
__device__ bf16 g_w1l[3 * DMODEL * DMODEL];
__device__ bf16 g_w2h[DMODEL * DMODEL];
__device__ bf16 g_w2l[DMODEL * DMODEL];
__device__ bf16 g_qkvh[MROWS * 3 * DMODEL];
__device__ bf16 g_qkvl[MROWS * 3 * DMODEL];
__device__ bf16 g_ah[MROWS * DMODEL];
__device__ bf16 g_al[MROWS * DMODEL];

__device__ __forceinline__ uint32_t smem_u32(const void* p) {
    return (uint32_t)__cvta_generic_to_shared(p);
}
__device__ __forceinline__ uint32_t pack2(float a, float b) {
    bf162 t;
    t.x = __float2bfloat16(a);
    t.y = __float2bfloat16(b);
    return *(uint32_t*)&t;
}

#define MMA_BF16(c, a, b)                                                      \
    asm volatile(                                                              \
        "mma.sync.aligned.m16n8k16.row.col.f32.bf16.bf16.f32 "                 \
        "{%0,%1,%2,%3},{%4,%5,%6,%7},{%8,%9},{%0,%1,%2,%3};"                   \
        : "+f"((c)[0]), "+f"((c)[1]), "+f"((c)[2]), "+f"((c)[3])               \
        : "r"((a)[0]), "r"((a)[1]), "r"((a)[2]), "r"((a)[3]),                  \
          "r"((b)[0]), "r"((b)[1]))

#define LDSM_X4(r, addr)                                                       \
    asm volatile("ldmatrix.sync.aligned.m8n8.x4.shared.b16 {%0,%1,%2,%3}, [%4];" \
                 : "=r"((r)[0]), "=r"((r)[1]), "=r"((r)[2]), "=r"((r)[3])      \
                 : "r"(addr))

#define LDSM_X2(r, addr)                                                       \
    asm volatile("ldmatrix.sync.aligned.m8n8.x2.shared.b16 {%0,%1}, [%2];"     \
                 : "=r"((r)[0]), "=r"((r)[1]) : "r"(addr))

#define CP_ASYNC16(dst, src)                                                   \
    asm volatile("cp.async.cg.shared.global [%0], [%1], 16;" ::"r"(dst), "l"(src))

// ---------------------------------------------------------------------------
// fp32 -> bf16 hi/lo split (elementwise)
// ---------------------------------------------------------------------------
__global__ void conv_split_kernel(const float* __restrict__ in,
                                  bf16* __restrict__ h, bf16* __restrict__ l,
                                  int n4)
{
    int i = blockIdx.x * blockDim.x + threadIdx.x;
    if (i < n4) {
        float4 v = ((const float4*)in)[i];
        bf16 h0 = __float2bfloat16(v.x), h1 = __float2bfloat16(v.y);
        bf16 h2 = __float2bfloat16(v.z), h3 = __float2bfloat16(v.w);
        bf162 hh0 = {h0, h1}, hh1 = {h2, h3};
        ((bf162*)h)[i * 2 + 0] = hh0;
        ((bf162*)h)[i * 2 + 1] = hh1;
        bf162 ll0 = {__float2bfloat16(v.x - __bfloat162float(h0)),
                     __float2bfloat16(v.y - __bfloat162float(h1))};
        bf162 ll1 = {__float2bfloat16(v.z - __bfloat162float(h2)),
                     __float2bfloat16(v.w - __bfloat162float(h3))};
        ((bf162*)l)[i * 2 + 0] = ll0;
        ((bf162*)l)[i * 2 + 1] = ll1;
    }
}

// Transpose + split: fp32 [K][N] -> bf16 [N][K] hi/lo
__global__ void conv_splitT_kernel(const float* __restrict__ in,
                                   bf16* __restrict__ h, bf16* __restrict__ l,
                                   int K, int N)
{
    __shared__ float t[32][33];
    int k0 = blockIdx.y * 32, n0 = blockIdx.x * 32;
    int tx = threadIdx.x, ty = threadIdx.y;
    #pragma unroll
    for (int i = 0; i < 4; ++i)
        t[ty + i * 8][tx] = in[(size_t)(k0 + ty + i * 8) * N + n0 + tx];
    __syncthreads();
    #pragma unroll
    for (int i = 0; i < 4; ++i) {
        float v = t[tx][ty + i * 8];
        int n = n0 + ty + i * 8;
        int k = k0 + tx;
        bf16 hv = __float2bfloat16(v);
        h[(size_t)n * K + k] = hv;
        l[(size_t)n * K + k] = __float2bfloat16(v - __bfloat162float(hv));
    }
}

// ---------------------------------------------------------------------------
// Tensor-core GEMM, bf16 2-term split (3 products), cp.async double-buffer.
// Tile 128x128x32, 256 threads, smem stride 40 (conflict-free ldmatrix).
// __launch_bounds__(256, 2): cap regs at 128 so 2 CTAs/SM fit (RF was the
// occupancy limiter at 136 regs). OUTBF16=1: emit bf16 hi/lo split; else fp32.
// ---------------------------------------------------------------------------
#define GS 40
#define STG_ELEMS (4 * 128 * GS)   // elems per stage (Ah,Al,Bh,Bl)

template <int OUTBF16>
__global__ __launch_bounds__(256, 2) void gemm_tc(
    const bf16* __restrict__ Ah, const bf16* __restrict__ Al,
    const bf16* __restrict__ Bh, const bf16* __restrict__ Bl,
    const float* __restrict__ bias,
    float* __restrict__ Cf, bf16* __restrict__ Ch, bf16* __restrict__ Cl,
    int M, int N, int K)
{
    extern __shared__ bf16 sm[];

    const int tid = threadIdx.x;
    const int warp = tid >> 5, lane = tid & 31;
    const int bm = blockIdx.y * 128, bn = blockIdx.x * 128;
    const int wm = (warp >> 2) * 64, wn = (warp & 3) * 32;
    const int lrow = tid >> 1, lcol = (tid & 1) * 16;

    const bf16* gsrc[4];
    gsrc[0] = Ah + (size_t)(bm + lrow) * K + lcol;
    gsrc[1] = Al + (size_t)(bm + lrow) * K + lcol;
    gsrc[2] = Bh + (size_t)(bn + lrow) * K + lcol;
    gsrc[3] = Bl + (size_t)(bn + lrow) * K + lcol;

    uint32_t sdst0[4];
    #pragma unroll
    for (int q = 0; q < 4; ++q)
        sdst0[q] = smem_u32(sm + q * 128 * GS + lrow * GS + lcol);

    float acc[4][4][4];
    #pragma unroll
    for (int i = 0; i < 4; ++i)
        #pragma unroll
        for (int j = 0; j < 4; ++j)
            #pragma unroll
            for (int r = 0; r < 4; ++r) acc[i][j][r] = 0.0f;

    const int nk = K >> 5;

    // stage 0  (each thread: 16 elems = two 16B chunks at +0 and +16 BYTES)
    #pragma unroll
    for (int q = 0; q < 4; ++q) {
        CP_ASYNC16(sdst0[q], gsrc[q]);
        CP_ASYNC16(sdst0[q] + 16, gsrc[q] + 8);
    }
    asm volatile("cp.async.commit_group;");
    asm volatile("cp.async.wait_group 0;");
    __syncthreads();

    for (int t = 0; t < nk; ++t) {
        if (t + 1 < nk) {
            uint32_t so = ((t + 1) & 1) * (STG_ELEMS * 2);   // byte offset of stage
            int off = (t + 1) * 32;
            #pragma unroll
            for (int q = 0; q < 4; ++q) {
                CP_ASYNC16(sdst0[q] + so, gsrc[q] + off);
                CP_ASYNC16(sdst0[q] + so + 16, gsrc[q] + off + 8);
            }
            asm volatile("cp.async.commit_group;");
        }

        const bf16* base = sm + (t & 1) * STG_ELEMS;
        const bf16* sAh = base;
        const bf16* sAl = base + 128 * GS;
        const bf16* sBh = base + 2 * 128 * GS;
        const bf16* sBl = base + 3 * 128 * GS;

        #pragma unroll
        for (int ks = 0; ks < 32; ks += 16) {
            uint32_t bh[4][2], bl[4][2];
            #pragma unroll
            for (int nt = 0; nt < 4; ++nt) {
                uint32_t ab = smem_u32(&sBh[(wn + nt * 8 + (lane & 7)) * GS +
                                            ks + ((lane >> 3) & 1) * 8]);
                LDSM_X2(bh[nt], ab);
                uint32_t ab2 = smem_u32(&sBl[(wn + nt * 8 + (lane & 7)) * GS +
                                             ks + ((lane >> 3) & 1) * 8]);
                LDSM_X2(bl[nt], ab2);
            }
            #pragma unroll
            for (int mt = 0; mt < 4; ++mt) {
                uint32_t afh[4], afl[4];
                uint32_t aa = smem_u32(&sAh[(wm + mt * 16 + (lane & 15)) * GS +
                                            ks + (lane >> 4) * 8]);
                LDSM_X4(afh, aa);
                uint32_t aa2 = smem_u32(&sAl[(wm + mt * 16 + (lane & 15)) * GS +
                                             ks + (lane >> 4) * 8]);
                LDSM_X4(afl, aa2);
                // 3 product passes, each acc touched once per pass ->
                // dependent reuses are 4 MMAs apart (independent chains)
                #pragma unroll
                for (int nt = 0; nt < 4; ++nt)
                    MMA_BF16(acc[mt][nt], afh, bh[nt]);
                #pragma unroll
                for (int nt = 0; nt < 4; ++nt)
                    MMA_BF16(acc[mt][nt], afh, bl[nt]);
                #pragma unroll
                for (int nt = 0; nt < 4; ++nt)
                    MMA_BF16(acc[mt][nt], afl, bh[nt]);
            }
        }
        asm volatile("cp.async.wait_group 0;");
        __syncthreads();
    }

    #pragma unroll
    for (int mt = 0; mt < 4; ++mt) {
        #pragma unroll
        for (int nt = 0; nt < 4; ++nt) {
            int row = bm + wm + mt * 16 + (lane >> 2);
            int col = bn + wn + nt * 8 + (lane & 3) * 2;
            float bx = bias[col], by = bias[col + 1];
            float v0 = acc[mt][nt][0] + bx, v1 = acc[mt][nt][1] + by;
            float v2 = acc[mt][nt][2] + bx, v3 = acc[mt][nt][3] + by;
            if (OUTBF16) {
                bf162 hh0; hh0.x = __float2bfloat16(v0); hh0.y = __float2bfloat16(v1);
                *(uint32_t*)(Ch + (size_t)row * N + col) = *(uint32_t*)&hh0;
                bf162 ll0 = {__float2bfloat16(v0 - __bfloat162float(hh0.x)),
                             __float2bfloat16(v1 - __bfloat162float(hh0.y))};
                *(uint32_t*)(Cl + (size_t)row * N + col) = *(uint32_t*)&ll0;
                bf162 hh1; hh1.x = __float2bfloat16(v2); hh1.y = __float2bfloat16(v3);
                *(uint32_t*)(Ch + (size_t)(row + 8) * N + col) = *(uint32_t*)&hh1;
                bf162 ll1 = {__float2bfloat16(v2 - __bfloat162float(hh1.x)),
                             __float2bfloat16(v3 - __bfloat162float(hh1.y))};
                *(uint32_t*)(Cl + (size_t)(row + 8) * N + col) = *(uint32_t*)&ll1;
            } else {
                float2 f0 = {v0, v1}, f1 = {v2, v3};
                *(float2*)(Cf + (size_t)row * N + col) = f0;
                *(float2*)(Cf + (size_t)(row + 8) * N + col) = f1;
            }
        }
    }
}

// ---------------------------------------------------------------------------
// Tensor-core sliding-window attention.
// CTA = (b, h, 64 queries), 128 threads = 4 warps, warp = 16 queries.
// S[16 x 128] = Q * K^T (bf16 3-product split), mask+softmax in registers,
// O[16 x 64] = P * V with P re-packed to A-fragments in registers.
// Emits bf16 hi/lo for the output projection.
// ---------------------------------------------------------------------------
#define A_KH 0
#define A_KL (128 * 72)
#define A_VTH (2 * 128 * 72)
#define A_VTL (2 * 128 * 72 + 64 * 136)
#define A_QH (2 * 128 * 72 + 2 * 64 * 136)
#define A_QL (2 * 128 * 72 + 2 * 64 * 136 + 64 * 72)
#define A_SMEM_ELEMS (2 * 128 * 72 + 2 * 64 * 136 + 2 * 64 * 72)   // 45056

__global__ __launch_bounds__(128) void attn_tc_kernel(
    const bf16* __restrict__ qkvh, const bf16* __restrict__ qkvl,
    bf16* __restrict__ outh, bf16* __restrict__ outl)
{
    extern __shared__ bf16 sm[];

    const int tid = threadIdx.x;
    const int warp = tid >> 5, lane = tid & 31;
    const int s0 = blockIdx.x * 64;
    const int h = blockIdx.y;
    const int b = blockIdx.z;

    // ---- load K rows + transposed V (window rows s0-32 .. s0+95) ----
    {
        int pos = s0 - 32 + tid;
        uint4* dkh = (uint4*)(sm + A_KH + tid * 72);
        uint4* dkl = (uint4*)(sm + A_KL + tid * 72);
        if (pos >= 0 && pos < SEQ) {
            size_t rowb = (size_t)(b * SEQ + pos) * (3 * DMODEL);
            const uint4* kh = (const uint4*)(qkvh + rowb + DMODEL + h * HDIM);
            const uint4* kl = (const uint4*)(qkvl + rowb + DMODEL + h * HDIM);
            #pragma unroll
            for (int i = 0; i < 8; ++i) { dkh[i] = kh[i]; dkl[i] = kl[i]; }
            const uint32_t* vh = (const uint32_t*)(qkvh + rowb + 2 * DMODEL + h * HDIM);
            const uint32_t* vl = (const uint32_t*)(qkvl + rowb + 2 * DMODEL + h * HDIM);
            #pragma unroll
            for (int i = 0; i < 32; ++i) {
                uint32_t ph = vh[i], pl = vl[i];
                bf162 th = *(bf162*)&ph, tl = *(bf162*)&pl;
                sm[A_VTH + (2 * i) * 136 + tid] = th.x;
                sm[A_VTH + (2 * i + 1) * 136 + tid] = th.y;
                sm[A_VTL + (2 * i) * 136 + tid] = tl.x;
                sm[A_VTL + (2 * i + 1) * 136 + tid] = tl.y;
            }
        } else {
            uint4 z = {0, 0, 0, 0};
            #pragma unroll
            for (int i = 0; i < 8; ++i) { dkh[i] = z; dkl[i] = z; }
            bf16 zb = __float2bfloat16(0.0f);
            #pragma unroll
            for (int d = 0; d < 64; ++d) {
                sm[A_VTH + d * 136 + tid] = zb;
                sm[A_VTL + d * 136 + tid] = zb;
            }
        }
        // Q: 2 threads per row, 32 dims each
        int qr = tid >> 1, qo = (tid & 1) * 32;
        size_t rq = (size_t)(b * SEQ + s0 + qr) * (3 * DMODEL) + h * HDIM + qo;
        const uint4* qh = (const uint4*)(qkvh + rq);
        const uint4* ql = (const uint4*)(qkvl + rq);
        uint4* dqh = (uint4*)(sm + A_QH + qr * 72 + qo);
        uint4* dql = (uint4*)(sm + A_QL + qr * 72 + qo);
        #pragma unroll
        for (int i = 0; i < 4; ++i) { dqh[i] = qh[i]; dql[i] = ql[i]; }
    }
    __syncthreads();

    // ---- S = Q K^T ----
    float s[16][4];
    #pragma unroll
    for (int nt = 0; nt < 16; ++nt)
        #pragma unroll
        for (int j = 0; j < 4; ++j) s[nt][j] = 0.0f;

    const int qrow = warp * 16 + (lane & 15);
    #pragma unroll
    for (int kk = 0; kk < 4; ++kk) {
        uint32_t ah[4], al[4];
        uint32_t aa = smem_u32(sm + A_QH + qrow * 72 + kk * 16 + (lane >> 4) * 8);
        LDSM_X4(ah, aa);
        uint32_t aa2 = smem_u32(sm + A_QL + qrow * 72 + kk * 16 + (lane >> 4) * 8);
        LDSM_X4(al, aa2);
        #pragma unroll
        for (int nt = 0; nt < 16; ++nt) {
            uint32_t bh[2], bl[2];
            uint32_t ba = smem_u32(sm + A_KH + (nt * 8 + (lane & 7)) * 72 +
                                   kk * 16 + ((lane >> 3) & 1) * 8);
            LDSM_X2(bh, ba);
            uint32_t ba2 = smem_u32(sm + A_KL + (nt * 8 + (lane & 7)) * 72 +
                                    kk * 16 + ((lane >> 3) & 1) * 8);
            LDSM_X2(bl, ba2);
            MMA_BF16(s[nt], ah, bh);
            MMA_BF16(s[nt], ah, bl);
            MMA_BF16(s[nt], al, bh);
        }
    }

    // ---- scale + mask + softmax ----
    const int m0 = warp * 16 + (lane >> 2);
    const int m1 = m0 + 8;
    float mx0 = -1e30f, mx1 = -1e30f;
    #pragma unroll
    for (int nt = 0; nt < 16; ++nt) {
        #pragma unroll
        for (int jj = 0; jj < 2; ++jj) {
            int nn = nt * 8 + (lane & 3) * 2 + jj;
            int gpos = s0 - 32 + nn;
            bool vp = (gpos >= 0) && (gpos < SEQ);
            int d0 = nn - m0;
            s[nt][jj] = (vp && d0 >= 0 && d0 <= 64) ? s[nt][jj] * 0.125f : -1e9f;
            int d1 = nn - m1;
            s[nt][2 + jj] = (vp && d1 >= 0 && d1 <= 64) ? s[nt][2 + jj] * 0.125f : -1e9f;
        }
        mx0 = fmaxf(mx0, fmaxf(s[nt][0], s[nt][1]));
        mx1 = fmaxf(mx1, fmaxf(s[nt][2], s[nt][3]));
    }
    mx0 = fmaxf(mx0, __shfl_xor_sync(0xffffffffu, mx0, 1));
    mx0 = fmaxf(mx0, __shfl_xor_sync(0xffffffffu, mx0, 2));
    mx1 = fmaxf(mx1, __shfl_xor_sync(0xffffffffu, mx1, 1));
    mx1 = fmaxf(mx1, __shfl_xor_sync(0xffffffffu, mx1, 2));

    float sum0 = 0.f, sum1 = 0.f;
    #pragma unroll
    for (int nt = 0; nt < 16; ++nt) {
        s[nt][0] = __expf(s[nt][0] - mx0); sum0 += s[nt][0];
        s[nt][1] = __expf(s[nt][1] - mx0); sum0 += s[nt][1];
        s[nt][2] = __expf(s[nt][2] - mx1); sum1 += s[nt][2];
        s[nt][3] = __expf(s[nt][3] - mx1); sum1 += s[nt][3];
    }
    sum0 += __shfl_xor_sync(0xffffffffu, sum0, 1);
    sum0 += __shfl_xor_sync(0xffffffffu, sum0, 2);
    sum1 += __shfl_xor_sync(0xffffffffu, sum1, 1);
    sum1 += __shfl_xor_sync(0xffffffffu, sum1, 2);
    float inv0 = 1.0f / sum0, inv1 = 1.0f / sum1;

    // ---- O = P V  (P re-packed from registers into A fragments) ----
    float o[8][4];
    #pragma unroll
    for (int nt = 0; nt < 8; ++nt)
        #pragma unroll
        for (int j = 0; j < 4; ++j) o[nt][j] = 0.0f;

    #pragma unroll
    for (int kt = 0; kt < 8; ++kt) {
        float* pa = s[2 * kt];
        float* pb = s[2 * kt + 1];
        uint32_t ah[4], al[4];
        ah[0] = pack2(pa[0], pa[1]);
        ah[1] = pack2(pa[2], pa[3]);
        ah[2] = pack2(pb[0], pb[1]);
        ah[3] = pack2(pb[2], pb[3]);
        {
            bf162 t0 = *(bf162*)&ah[0], t1 = *(bf162*)&ah[1];
            bf162 t2 = *(bf162*)&ah[2], t3 = *(bf162*)&ah[3];
            al[0] = pack2(pa[0] - __bfloat162float(t0.x), pa[1] - __bfloat162float(t0.y));
            al[1] = pack2(pa[2] - __bfloat162float(t1.x), pa[3] - __bfloat162float(t1.y));
            al[2] = pack2(pb[0] - __bfloat162float(t2.x), pb[1] - __bfloat162float(t2.y));
            al[3] = pack2(pb[2] - __bfloat162float(t3.x), pb[3] - __bfloat162float(t3.y));
        }
        #pragma unroll
        for (int nt2 = 0; nt2 < 8; ++nt2) {
            uint32_t bh[2], bl[2];
            uint32_t ba = smem_u32(sm + A_VTH + (nt2 * 8 + (lane & 7)) * 136 +
                                   kt * 16 + ((lane >> 3) & 1) * 8);
            LDSM_X2(bh, ba);
            uint32_t ba2 = smem_u32(sm + A_VTL + (nt2 * 8 + (lane & 7)) * 136 +
                                    kt * 16 + ((lane >> 3) & 1) * 8);
            LDSM_X2(bl, ba2);
            MMA_BF16(o[nt2], ah, bh);
            MMA_BF16(o[nt2], ah, bl);
            MMA_BF16(o[nt2], al, bh);
        }
    }

    // ---- normalize + emit bf16 hi/lo ----
    size_t r0 = (size_t)(b * SEQ + s0 + m0) * DMODEL + h * HDIM;
    size_t r1 = r0 + (size_t)8 * DMODEL;
    #pragma unroll
    for (int nt2 = 0; nt2 < 8; ++nt2) {
        int d = nt2 * 8 + (lane & 3) * 2;
        float v0 = o[nt2][0] * inv0, v1 = o[nt2][1] * inv0;
        float v2 = o[nt2][2] * inv1, v3 = o[nt2][3] * inv1;
        uint32_t hh0 = pack2(v0, v1);
        bf162 th0 = *(bf162*)&hh0;
        *(uint32_t*)(outh + r0 + d) = hh0;
        *(uint32_t*)(outl + r0 + d) =
            pack2(v0 - __bfloat162float(th0.x), v1 - __bfloat162float(th0.y));
        uint32_t hh1 = pack2(v2, v3);
        bf162 th1 = *(bf162*)&hh1;
        *(uint32_t*)(outh + r1 + d) = hh1;
        *(uint32_t*)(outl + r1 + d) =
            pack2(v2 - __bfloat162float(th1.x), v3 - __bfloat162float(th1.y));
    }
}

// ---------------------------------------------------------------------------
// Launch
// ---------------------------------------------------------------------------
extern "C" void kernel_launch(void* const* d_in, const int* in_sizes, int n_in,
                              void* d_out, int out_size)
{
    const float* x     = (const float*)d_in[0];
    const float* w_qkv = (const float*)d_in[1];
    const float* b_qkv = (const float*)d_in[2];
    const float* w_out = (const float*)d_in[3];
    const float* b_out = (const float*)d_in[4];
    float* out         = (float*)d_out;

    bf16 *xh, *xl, *w1h, *w1l, *w2h, *w2l, *qh, *ql, *ah, *al;
    cudaGetSymbolAddress((void**)&xh, g_xh);
    cudaGetSymbolAddress((void**)&xl, g_xl);
    cudaGetSymbolAddress((void**)&w1h, g_w1h);
    cudaGetSymbolAddress((void**)&w1l, g_w1l);
    cudaGetSymbolAddress((void**)&w2h, g_w2h);
    cudaGetSymbolAddress((void**)&w2l, g_w2l);
    cudaGetSymbolAddress((void**)&qh, g_qkvh);
    cudaGetSymbolAddress((void**)&ql, g_qkvl);
    cudaGetSymbolAddress((void**)&ah, g_ah);
    cudaGetSymbolAddress((void**)&al, g_al);

    const int M = MROWS;

    {
        int n4 = (M * DMODEL) / 4;
        conv_split_kernel<<<(n4 + 255) / 256, 256>>>(x, xh, xl, n4);
    }
    {
        dim3 blk(32, 8);
        conv_splitT_kernel<<<dim3((3 * DMODEL) / 32, DMODEL / 32), blk>>>(
            w_qkv, w1h, w1l, DMODEL, 3 * DMODEL);
        conv_splitT_kernel<<<dim3(DMODEL / 32, DMODEL / 32), blk>>>(
            w_out, w2h, w2l, DMODEL, DMODEL);
    }

    const int gemm_smem = 2 * STG_ELEMS * (int)sizeof(bf16);   // 81920
    cudaFuncSetAttribute(gemm_tc<1>, cudaFuncAttributeMaxDynamicSharedMemorySize, gemm_smem);
    cudaFuncSetAttribute(gemm_tc<0>, cudaFuncAttributeMaxDynamicSharedMemorySize, gemm_smem);

    // GEMM1: qkv (bf16 hi/lo) = x @ w_qkv + b_qkv
    {
        dim3 grid((3 * DMODEL) / 128, M / 128);
        gemm_tc<1><<<grid, 256, gemm_smem>>>(xh, xl, w1h, w1l, b_qkv,
                                             nullptr, qh, ql, M, 3 * DMODEL, DMODEL);
    }

    // attention (tensor core)
    {
        int smem = A_SMEM_ELEMS * (int)sizeof(bf16);   // 90112
        cudaFuncSetAttribute(attn_tc_kernel,
                             cudaFuncAttributeMaxDynamicSharedMemorySize, smem);
        dim3 grid(SEQ / 64, NHEAD, BATCH);
        attn_tc_kernel<<<grid, 128, smem>>>(qh, ql, ah, al);
    }

    // GEMM2: out (fp32) = attn @ w_out + b_out
    {
        dim3 grid(DMODEL / 128, M / 128);
        gemm_tc<0><<<grid, 256, gemm_smem>>>(ah, al, w2h, w2l, b_out,
                                             out, nullptr, nullptr, M, DMODEL, DMODEL);
    }
}

// round 12
// speedup vs baseline: 1.8178x; 1.0016x over previous
#include <cuda_runtime.h>
#include <cuda_bf16.h>
#include <math.h>
#include <stdint.h>

#define BATCH 2
#define SEQ   2048
#define DMODEL 512
#define NHEAD 8
#define HDIM  64
#define MROWS (BATCH * SEQ)   // 4096

typedef __nv_bfloat16 bf16;
typedef __nv_bfloat162 bf162;

// ---------------------------------------------------------------------------
// Device-global scratch
// ---------------------------------------------------------------------------
__device__ bf16 g_xh[MROWS * DMODEL];
__device__ bf16 g_xl[MROWS * DMODEL];
__device__ bf16 g_w1h[3 * DMODEL * DMODEL];
__device__ bf16 g_w1l[3 * DMODEL * DMODEL];
__device__ bf16 g_w2h[DMODEL * DMODEL];
__device__ bf16 g_w2l[DMODEL * DMODEL];
__device__ bf16 g_qkvh[MROWS * 3 * DMODEL];
__device__ bf16 g_qkvl[MROWS * 3 * DMODEL];
__device__ bf16 g_ah[MROWS * DMODEL];
__device__ bf16 g_al[MROWS * DMODEL];

__device__ __forceinline__ uint32_t smem_u32(const void* p) {
    return (uint32_t)__cvta_generic_to_shared(p);
}
__device__ __forceinline__ uint32_t pack2(float a, float b) {
    bf162 t;
    t.x = __float2bfloat16(a);
    t.y = __float2bfloat16(b);
    return *(uint32_t*)&t;
}

#define MMA_BF16(c, a, b)                                                      \
    asm volatile(                                                              \
        "mma.sync.aligned.m16n8k16.row.col.f32.bf16.bf16.f32 "                 \
        "{%0,%1,%2,%3},{%4,%5,%6,%7},{%8,%9},{%0,%1,%2,%3};"                   \
        : "+f"((c)[0]), "+f"((c)[1]), "+f"((c)[2]), "+f"((c)[3])               \
        : "r"((a)[0]), "r"((a)[1]), "r"((a)[2]), "r"((a)[3]),                  \
          "r"((b)[0]), "r"((b)[1]))

#define LDSM_X4(r, addr)                                                       \
    asm volatile("ldmatrix.sync.aligned.m8n8.x4.shared.b16 {%0,%1,%2,%3}, [%4];" \
                 : "=r"((r)[0]), "=r"((r)[1]), "=r"((r)[2]), "=r"((r)[3])      \
                 : "r"(addr))

#define LDSM_X2(r, addr)                                                       \
    asm volatile("ldmatrix.sync.aligned.m8n8.x2.shared.b16 {%0,%1}, [%2];"     \
                 : "=r"((r)[0]), "=r"((r)[1]) : "r"(addr))

#define LDSM_X2T(r, addr)                                                      \
    asm volatile("ldmatrix.sync.aligned.m8n8.x2.trans.shared.b16 {%0,%1}, [%2];" \
                 : "=r"((r)[0]), "=r"((r)[1]) : "r"(addr))

#define CP_ASYNC16(dst, src)                                                   \
    asm volatile("cp.async.cg.shared.global [%0], [%1], 16;" ::"r"(dst), "l"(src))

// ---------------------------------------------------------------------------
// fp32 -> bf16 hi/lo split (elementwise)
// ---------------------------------------------------------------------------
__global__ void conv_split_kernel(const float* __restrict__ in,
                                  bf16* __restrict__ h, bf16* __restrict__ l,
                                  int n4)
{
    int i = blockIdx.x * blockDim.x + threadIdx.x;
    if (i < n4) {
        float4 v = ((const float4*)in)[i];
        bf16 h0 = __float2bfloat16(v.x), h1 = __float2bfloat16(v.y);
        bf16 h2 = __float2bfloat16(v.z), h3 = __float2bfloat16(v.w);
        bf162 hh0 = {h0, h1}, hh1 = {h2, h3};
        ((bf162*)h)[i * 2 + 0] = hh0;
        ((bf162*)h)[i * 2 + 1] = hh1;
        bf162 ll0 = {__float2bfloat16(v.x - __bfloat162float(h0)),
                     __float2bfloat16(v.y - __bfloat162float(h1))};
        bf162 ll1 = {__float2bfloat16(v.z - __bfloat162float(h2)),
                     __float2bfloat16(v.w - __bfloat162float(h3))};
        ((bf162*)l)[i * 2 + 0] = ll0;
        ((bf162*)l)[i * 2 + 1] = ll1;
    }
}

// Transpose + split: fp32 [K][N] -> bf16 [N][K] hi/lo
__global__ void conv_splitT_kernel(const float* __restrict__ in,
                                   bf16* __restrict__ h, bf16* __restrict__ l,
                                   int K, int N)
{
    __shared__ float t[32][33];
    int k0 = blockIdx.y * 32, n0 = blockIdx.x * 32;
    int tx = threadIdx.x, ty = threadIdx.y;
    #pragma unroll
    for (int i = 0; i < 4; ++i)
        t[ty + i * 8][tx] = in[(size_t)(k0 + ty + i * 8) * N + n0 + tx];
    __syncthreads();
    #pragma unroll
    for (int i = 0; i < 4; ++i) {
        float v = t[tx][ty + i * 8];
        int n = n0 + ty + i * 8;
        int k = k0 + tx;
        bf16 hv = __float2bfloat16(v);
        h[(size_t)n * K + k] = hv;
        l[(size_t)n * K + k] = __float2bfloat16(v - __bfloat162float(hv));
    }
}

// ---------------------------------------------------------------------------
// Tensor-core GEMM (mma.sync), bf16 2-term split (3 products), cp.async
// double-buffer. Tile 128x128x32, 256 threads, smem stride 40.
// mt processed in pairs so accumulator reuse distance is 8 MMAs.
// ---------------------------------------------------------------------------
#define GS 40
#define STG_ELEMS (4 * 128 * GS)   // elems per stage (Ah,Al,Bh,Bl)

template <int OUTBF16>
__global__ __launch_bounds__(256, 2) void gemm_tc(
    const bf16* __restrict__ Ah, const bf16* __restrict__ Al,
    const bf16* __restrict__ Bh, const bf16* __restrict__ Bl,
    const float* __restrict__ bias,
    float* __restrict__ Cf, bf16* __restrict__ Ch, bf16* __restrict__ Cl,
    int M, int N, int K)
{
    extern __shared__ bf16 sm[];

    const int tid = threadIdx.x;
    const int warp = tid >> 5, lane = tid & 31;
    const int bm = blockIdx.y * 128, bn = blockIdx.x * 128;
    const int wm = (warp >> 2) * 64, wn = (warp & 3) * 32;
    const int lrow = tid >> 1, lcol = (tid & 1) * 16;

    const bf16* gsrc[4];
    gsrc[0] = Ah + (size_t)(bm + lrow) * K + lcol;
    gsrc[1] = Al + (size_t)(bm + lrow) * K + lcol;
    gsrc[2] = Bh + (size_t)(bn + lrow) * K + lcol;
    gsrc[3] = Bl + (size_t)(bn + lrow) * K + lcol;

    uint32_t sdst0[4];
    #pragma unroll
    for (int q = 0; q < 4; ++q)
        sdst0[q] = smem_u32(sm + q * 128 * GS + lrow * GS + lcol);

    float acc[4][4][4];
    #pragma unroll
    for (int i = 0; i < 4; ++i)
        #pragma unroll
        for (int j = 0; j < 4; ++j)
            #pragma unroll
            for (int r = 0; r < 4; ++r) acc[i][j][r] = 0.0f;

    const int nk = K >> 5;

    // stage 0  (each thread: 16 elems = two 16B chunks at +0 and +16 BYTES)
    #pragma unroll
    for (int q = 0; q < 4; ++q) {
        CP_ASYNC16(sdst0[q], gsrc[q]);
        CP_ASYNC16(sdst0[q] + 16, gsrc[q] + 8);
    }
    asm volatile("cp.async.commit_group;");
    asm volatile("cp.async.wait_group 0;");
    __syncthreads();

    for (int t = 0; t < nk; ++t) {
        if (t + 1 < nk) {
            uint32_t so = ((t + 1) & 1) * (STG_ELEMS * 2);   // byte offset of stage
            int off = (t + 1) * 32;
            #pragma unroll
            for (int q = 0; q < 4; ++q) {
                CP_ASYNC16(sdst0[q] + so, gsrc[q] + off);
                CP_ASYNC16(sdst0[q] + so + 16, gsrc[q] + off + 8);
            }
            asm volatile("cp.async.commit_group;");
        }

        const bf16* base = sm + (t & 1) * STG_ELEMS;
        const bf16* sAh = base;
        const bf16* sAl = base + 128 * GS;
        const bf16* sBh = base + 2 * 128 * GS;
        const bf16* sBl = base + 3 * 128 * GS;

        #pragma unroll
        for (int ks = 0; ks < 32; ks += 16) {
            uint32_t bh[4][2], bl[4][2];
            #pragma unroll
            for (int nt = 0; nt < 4; ++nt) {
                uint32_t ab = smem_u32(&sBh[(wn + nt * 8 + (lane & 7)) * GS +
                                            ks + ((lane >> 3) & 1) * 8]);
                LDSM_X2(bh[nt], ab);
                uint32_t ab2 = smem_u32(&sBl[(wn + nt * 8 + (lane & 7)) * GS +
                                             ks + ((lane >> 3) & 1) * 8]);
                LDSM_X2(bl[nt], ab2);
            }
            #pragma unroll
            for (int mtp = 0; mtp < 4; mtp += 2) {
                uint32_t afh0[4], afl0[4], afh1[4], afl1[4];
                uint32_t a0 = smem_u32(&sAh[(wm + mtp * 16 + (lane & 15)) * GS +
                                            ks + (lane >> 4) * 8]);
                LDSM_X4(afh0, a0);
                uint32_t a1 = smem_u32(&sAl[(wm + mtp * 16 + (lane & 15)) * GS +
                                            ks + (lane >> 4) * 8]);
                LDSM_X4(afl0, a1);
                uint32_t a2 = smem_u32(&sAh[(wm + (mtp + 1) * 16 + (lane & 15)) * GS +
                                            ks + (lane >> 4) * 8]);
                LDSM_X4(afh1, a2);
                uint32_t a3 = smem_u32(&sAl[(wm + (mtp + 1) * 16 + (lane & 15)) * GS +
                                            ks + (lane >> 4) * 8]);
                LDSM_X4(afl1, a3);
                // pass hh: 8 independent MMAs
                #pragma unroll
                for (int nt = 0; nt < 4; ++nt)
                    MMA_BF16(acc[mtp][nt], afh0, bh[nt]);
                #pragma unroll
                for (int nt = 0; nt < 4; ++nt)
                    MMA_BF16(acc[mtp + 1][nt], afh1, bh[nt]);
                // pass hl
                #pragma unroll
                for (int nt = 0; nt < 4; ++nt)
                    MMA_BF16(acc[mtp][nt], afh0, bl[nt]);
                #pragma unroll
                for (int nt = 0; nt < 4; ++nt)
                    MMA_BF16(acc[mtp + 1][nt], afh1, bl[nt]);
                // pass lh
                #pragma unroll
                for (int nt = 0; nt < 4; ++nt)
                    MMA_BF16(acc[mtp][nt], afl0, bh[nt]);
                #pragma unroll
                for (int nt = 0; nt < 4; ++nt)
                    MMA_BF16(acc[mtp + 1][nt], afl1, bh[nt]);
            }
        }
        asm volatile("cp.async.wait_group 0;");
        __syncthreads();
    }

    #pragma unroll
    for (int mt = 0; mt < 4; ++mt) {
        #pragma unroll
        for (int nt = 0; nt < 4; ++nt) {
            int row = bm + wm + mt * 16 + (lane >> 2);
            int col = bn + wn + nt * 8 + (lane & 3) * 2;
            float bx = bias[col], by = bias[col + 1];
            float v0 = acc[mt][nt][0] + bx, v1 = acc[mt][nt][1] + by;
            float v2 = acc[mt][nt][2] + bx, v3 = acc[mt][nt][3] + by;
            if (OUTBF16) {
                bf162 hh0; hh0.x = __float2bfloat16(v0); hh0.y = __float2bfloat16(v1);
                *(uint32_t*)(Ch + (size_t)row * N + col) = *(uint32_t*)&hh0;
                bf162 ll0 = {__float2bfloat16(v0 - __bfloat162float(hh0.x)),
                             __float2bfloat16(v1 - __bfloat162float(hh0.y))};
                *(uint32_t*)(Cl + (size_t)row * N + col) = *(uint32_t*)&ll0;
                bf162 hh1; hh1.x = __float2bfloat16(v2); hh1.y = __float2bfloat16(v3);
                *(uint32_t*)(Ch + (size_t)(row + 8) * N + col) = *(uint32_t*)&hh1;
                bf162 ll1 = {__float2bfloat16(v2 - __bfloat162float(hh1.x)),
                             __float2bfloat16(v3 - __bfloat162float(hh1.y))};
                *(uint32_t*)(Cl + (size_t)(row + 8) * N + col) = *(uint32_t*)&ll1;
            } else {
                float2 f0 = {v0, v1}, f1 = {v2, v3};
                *(float2*)(Cf + (size_t)row * N + col) = f0;
                *(float2*)(Cf + (size_t)(row + 8) * N + col) = f1;
            }
        }
    }
}

// ---------------------------------------------------------------------------
// Tensor-core sliding-window attention (mma.sync).
// V stored ROW-MAJOR; P*V uses ldmatrix.x2.trans for B fragments.
// ---------------------------------------------------------------------------
#define A_KH 0
#define A_KL (128 * 72)
#define A_VH (2 * 128 * 72)
#define A_VL (3 * 128 * 72)
#define A_QH (4 * 128 * 72)
#define A_QL (4 * 128 * 72 + 64 * 72)
#define A_SMEM_ELEMS (4 * 128 * 72 + 2 * 64 * 72)   // 46080 elems = 92160 B

__global__ __launch_bounds__(128) void attn_tc_kernel(
    const bf16* __restrict__ qkvh, const bf16* __restrict__ qkvl,
    bf16* __restrict__ outh, bf16* __restrict__ outl)
{
    extern __shared__ bf16 sm[];

    const int tid = threadIdx.x;
    const int warp = tid >> 5, lane = tid & 31;
    const int s0 = blockIdx.x * 64;
    const int h = blockIdx.y;
    const int b = blockIdx.z;

    // ---- load K and V rows (window rows s0-32 .. s0+95), row-major ----
    {
        int pos = s0 - 32 + tid;
        uint4* dkh = (uint4*)(sm + A_KH + tid * 72);
        uint4* dkl = (uint4*)(sm + A_KL + tid * 72);
        uint4* dvh = (uint4*)(sm + A_VH + tid * 72);
        uint4* dvl = (uint4*)(sm + A_VL + tid * 72);
        if (pos >= 0 && pos < SEQ) {
            size_t rowb = (size_t)(b * SEQ + pos) * (3 * DMODEL);
            const uint4* kh = (const uint4*)(qkvh + rowb + DMODEL + h * HDIM);
            const uint4* kl = (const uint4*)(qkvl + rowb + DMODEL + h * HDIM);
            const uint4* vh = (const uint4*)(qkvh + rowb + 2 * DMODEL + h * HDIM);
            const uint4* vl = (const uint4*)(qkvl + rowb + 2 * DMODEL + h * HDIM);
            #pragma unroll
            for (int i = 0; i < 8; ++i) {
                dkh[i] = kh[i]; dkl[i] = kl[i];
                dvh[i] = vh[i]; dvl[i] = vl[i];
            }
        } else {
            uint4 z = {0, 0, 0, 0};
            #pragma unroll
            for (int i = 0; i < 8; ++i) {
                dkh[i] = z; dkl[i] = z; dvh[i] = z; dvl[i] = z;
            }
        }
        // Q: 2 threads per row, 32 dims each
        int qr = tid >> 1, qo = (tid & 1) * 32;
        size_t rq = (size_t)(b * SEQ + s0 + qr) * (3 * DMODEL) + h * HDIM + qo;
        const uint4* qh = (const uint4*)(qkvh + rq);
        const uint4* ql = (const uint4*)(qkvl + rq);
        uint4* dqh = (uint4*)(sm + A_QH + qr * 72 + qo);
        uint4* dql = (uint4*)(sm + A_QL + qr * 72 + qo);
        #pragma unroll
        for (int i = 0; i < 4; ++i) { dqh[i] = qh[i]; dql[i] = ql[i]; }
    }
    __syncthreads();

    // ---- S = Q K^T ----
    float s[16][4];
    #pragma unroll
    for (int nt = 0; nt < 16; ++nt)
        #pragma unroll
        for (int j = 0; j < 4; ++j) s[nt][j] = 0.0f;

    const int qrow = warp * 16 + (lane & 15);
    #pragma unroll
    for (int kk = 0; kk < 4; ++kk) {
        uint32_t ah[4], al[4];
        uint32_t aa = smem_u32(sm + A_QH + qrow * 72 + kk * 16 + (lane >> 4) * 8);
        LDSM_X4(ah, aa);
        uint32_t aa2 = smem_u32(sm + A_QL + qrow * 72 + kk * 16 + (lane >> 4) * 8);
        LDSM_X4(al, aa2);
        #pragma unroll
        for (int nt = 0; nt < 16; ++nt) {
            uint32_t bh[2], bl[2];
            uint32_t ba = smem_u32(sm + A_KH + (nt * 8 + (lane & 7)) * 72 +
                                   kk * 16 + ((lane >> 3) & 1) * 8);
            LDSM_X2(bh, ba);
            uint32_t ba2 = smem_u32(sm + A_KL + (nt * 8 + (lane & 7)) * 72 +
                                    kk * 16 + ((lane >> 3) & 1) * 8);
            LDSM_X2(bl, ba2);
            MMA_BF16(s[nt], ah, bh);
            MMA_BF16(s[nt], ah, bl);
            MMA_BF16(s[nt], al, bh);
        }
    }

    // ---- scale + mask + softmax ----
    const int m0 = warp * 16 + (lane >> 2);
    const int m1 = m0 + 8;
    float mx0 = -1e30f, mx1 = -1e30f;
    #pragma unroll
    for (int nt = 0; nt < 16; ++nt) {
        #pragma unroll
        for (int jj = 0; jj < 2; ++jj) {
            int nn = nt * 8 + (lane & 3) * 2 + jj;
            int gpos = s0 - 32 + nn;
            bool vp = (gpos >= 0) && (gpos < SEQ);
            int d0 = nn - m0;
            s[nt][jj] = (vp && d0 >= 0 && d0 <= 64) ? s[nt][jj] * 0.125f : -1e9f;
            int d1 = nn - m1;
            s[nt][2 + jj] = (vp && d1 >= 0 && d1 <= 64) ? s[nt][2 + jj] * 0.125f : -1e9f;
        }
        mx0 = fmaxf(mx0, fmaxf(s[nt][0], s[nt][1]));
        mx1 = fmaxf(mx1, fmaxf(s[nt][2], s[nt][3]));
    }
    mx0 = fmaxf(mx0, __shfl_xor_sync(0xffffffffu, mx0, 1));
    mx0 = fmaxf(mx0, __shfl_xor_sync(0xffffffffu, mx0, 2));
    mx1 = fmaxf(mx1, __shfl_xor_sync(0xffffffffu, mx1, 1));
    mx1 = fmaxf(mx1, __shfl_xor_sync(0xffffffffu, mx1, 2));

    float sum0 = 0.f, sum1 = 0.f;
    #pragma unroll
    for (int nt = 0; nt < 16; ++nt) {
        s[nt][0] = __expf(s[nt][0] - mx0); sum0 += s[nt][0];
        s[nt][1] = __expf(s[nt][1] - mx0); sum0 += s[nt][1];
        s[nt][2] = __expf(s[nt][2] - mx1); sum1 += s[nt][2];
        s[nt][3] = __expf(s[nt][3] - mx1); sum1 += s[nt][3];
    }
    sum0 += __shfl_xor_sync(0xffffffffu, sum0, 1);
    sum0 += __shfl_xor_sync(0xffffffffu, sum0, 2);
    sum1 += __shfl_xor_sync(0xffffffffu, sum1, 1);
    sum1 += __shfl_xor_sync(0xffffffffu, sum1, 2);
    float inv0 = 1.0f / sum0, inv1 = 1.0f / sum1;

    // ---- O = P V (P re-packed to A fragments; V via ldmatrix.trans) ----
    float o[8][4];
    #pragma unroll
    for (int nt = 0; nt < 8; ++nt)
        #pragma unroll
        for (int j = 0; j < 4; ++j) o[nt][j] = 0.0f;

    #pragma unroll
    for (int kt = 0; kt < 8; ++kt) {
        float* pa = s[2 * kt];
        float* pb = s[2 * kt + 1];
        uint32_t ah[4], al[4];
        ah[0] = pack2(pa[0], pa[1]);
        ah[1] = pack2(pa[2], pa[3]);
        ah[2] = pack2(pb[0], pb[1]);
        ah[3] = pack2(pb[2], pb[3]);
        {
            bf162 t0 = *(bf162*)&ah[0], t1 = *(bf162*)&ah[1];
            bf162 t2 = *(bf162*)&ah[2], t3 = *(bf162*)&ah[3];
            al[0] = pack2(pa[0] - __bfloat162float(t0.x), pa[1] - __bfloat162float(t0.y));
            al[1] = pack2(pa[2] - __bfloat162float(t1.x), pa[3] - __bfloat162float(t1.y));
            al[2] = pack2(pb[0] - __bfloat162float(t2.x), pb[1] - __bfloat162float(t2.y));
            al[3] = pack2(pb[2] - __bfloat162float(t3.x), pb[3] - __bfloat162float(t3.y));
        }
        // B fragments from row-major V via trans: window rows kt*16..+15
        uint32_t vrow = (uint32_t)(kt * 16 + (lane & 15)) * 72;
        #pragma unroll
        for (int nt2 = 0; nt2 < 8; ++nt2) {
            uint32_t bh[2], bl[2];
            uint32_t ba = smem_u32(sm + A_VH + vrow + nt2 * 8);
            LDSM_X2T(bh, ba);
            uint32_t ba2 = smem_u32(sm + A_VL + vrow + nt2 * 8);
            LDSM_X2T(bl, ba2);
            MMA_BF16(o[nt2], ah, bh);
            MMA_BF16(o[nt2], ah, bl);
            MMA_BF16(o[nt2], al, bh);
        }
    }

    // ---- normalize + emit bf16 hi/lo ----
    size_t r0 = (size_t)(b * SEQ + s0 + m0) * DMODEL + h * HDIM;
    size_t r1 = r0 + (size_t)8 * DMODEL;
    #pragma unroll
    for (int nt2 = 0; nt2 < 8; ++nt2) {
        int d = nt2 * 8 + (lane & 3) * 2;
        float v0 = o[nt2][0] * inv0, v1 = o[nt2][1] * inv0;
        float v2 = o[nt2][2] * inv1, v3 = o[nt2][3] * inv1;
        uint32_t hh0 = pack2(v0, v1);
        bf162 th0 = *(bf162*)&hh0;
        *(uint32_t*)(outh + r0 + d) = hh0;
        *(uint32_t*)(outl + r0 + d) =
            pack2(v0 - __bfloat162float(th0.x), v1 - __bfloat162float(th0.y));
        uint32_t hh1 = pack2(v2, v3);
        bf162 th1 = *(bf162*)&hh1;
        *(uint32_t*)(outh + r1 + d) = hh1;
        *(uint32_t*)(outl + r1 + d) =
            pack2(v2 - __bfloat162float(th1.x), v3 - __bfloat162float(th1.y));
    }
}

// ---------------------------------------------------------------------------
// Launch
// ---------------------------------------------------------------------------
extern "C" void kernel_launch(void* const* d_in, const int* in_sizes, int n_in,
                              void* d_out, int out_size)
{
    const float* x     = (const float*)d_in[0];
    const float* w_qkv = (const float*)d_in[1];
    const float* b_qkv = (const float*)d_in[2];
    const float* w_out = (const float*)d_in[3];
    const float* b_out = (const float*)d_in[4];
    float* out         = (float*)d_out;

    bf16 *xh, *xl, *w1h, *w1l, *w2h, *w2l, *qh, *ql, *ah, *al;
    cudaGetSymbolAddress((void**)&xh, g_xh);
    cudaGetSymbolAddress((void**)&xl, g_xl);
    cudaGetSymbolAddress((void**)&w1h, g_w1h);
    cudaGetSymbolAddress((void**)&w1l, g_w1l);
    cudaGetSymbolAddress((void**)&w2h, g_w2h);
    cudaGetSymbolAddress((void**)&w2l, g_w2l);
    cudaGetSymbolAddress((void**)&qh, g_qkvh);
    cudaGetSymbolAddress((void**)&ql, g_qkvl);
    cudaGetSymbolAddress((void**)&ah, g_ah);
    cudaGetSymbolAddress((void**)&al, g_al);

    const int M = MROWS;

    {
        int n4 = (M * DMODEL) / 4;
        conv_split_kernel<<<(n4 + 255) / 256, 256>>>(x, xh, xl, n4);
    }
    {
        dim3 blk(32, 8);
        conv_splitT_kernel<<<dim3((3 * DMODEL) / 32, DMODEL / 32), blk>>>(
            w_qkv, w1h, w1l, DMODEL, 3 * DMODEL);
        conv_splitT_kernel<<<dim3(DMODEL / 32, DMODEL / 32), blk>>>(
            w_out, w2h, w2l, DMODEL, DMODEL);
    }

    const int gemm_smem = 2 * STG_ELEMS * (int)sizeof(bf16);   // 81920
    cudaFuncSetAttribute(gemm_tc<1>, cudaFuncAttributeMaxDynamicSharedMemorySize, gemm_smem);
    cudaFuncSetAttribute(gemm_tc<0>, cudaFuncAttributeMaxDynamicSharedMemorySize, gemm_smem);

    // GEMM1: qkv (bf16 hi/lo) = x @ w_qkv + b_qkv
    {
        dim3 grid((3 * DMODEL) / 128, M / 128);
        gemm_tc<1><<<grid, 256, gemm_smem>>>(xh, xl, w1h, w1l, b_qkv,
                                             nullptr, qh, ql, M, 3 * DMODEL, DMODEL);
    }

    // attention (mma.sync tensor core)
    {
        int smem = A_SMEM_ELEMS * (int)sizeof(bf16);   // 92160
        cudaFuncSetAttribute(attn_tc_kernel,
                             cudaFuncAttributeMaxDynamicSharedMemorySize, smem);
        dim3 grid(SEQ / 64, NHEAD, BATCH);
        attn_tc_kernel<<<grid, 128, smem>>>(qh, ql, ah, al);
    }

    // GEMM2: out (fp32) = attn @ w_out + b_out
    {
        dim3 grid(DMODEL / 128, M / 128);
        gemm_tc<0><<<grid, 256, gemm_smem>>>(ah, al, w2h, w2l, b_out,
                                             out, nullptr, nullptr, M, DMODEL, DMODEL);
    }
}